// round 1
// baseline (speedup 1.0000x reference)
#include <cuda_runtime.h>
#include <cuda_bf16.h>
#include <cstdint>

#define NN 50000
#define NE 800000

// ------------------------- scratch (device globals) -------------------------
__device__ float    g_feat[NN * 256];   // GEMM output of current layer
__device__ float    g_h[NN * 256];      // hidden state (layer input / aggregate output)
__device__ float    g_el[NN * 4];
__device__ float    g_er[NN * 4];
__device__ float    g_e[NE * 4];        // edge logits -> exp values
__device__ unsigned g_mu[NN * 4];       // segment max (ordered-uint encoding)
__device__ float    g_mf[NN * 4];       // decoded segment max
__device__ float    g_s[NN * 4];        // segment sum

// ------------------------- GEMM: C[n,kout] = A[n,kin] @ W[kin,kout] ----------
// 64x64 tile, BK=16, 256 threads, 4x4 per-thread microtile, fp32.
#define BM 64
#define BN 64
#define BK 16

__global__ void gemm_tiled(const float* __restrict__ A, const float* __restrict__ W,
                           float* __restrict__ C, int n, int kin, int kout) {
    __shared__ float As[BK][BM + 4];   // transposed A tile, padded stride 68
    __shared__ float Ws[BK][BN];

    int tid = threadIdx.x;
    int tx = tid & 15, ty = tid >> 4;
    int rowBase = blockIdx.y * BM;
    int colBase = blockIdx.x * BN;

    int lr = tid >> 2;            // A-load row within tile (0..63)
    int lc = (tid & 3) * 4;       // A-load col (0,4,8,12)
    int wr = tid >> 4;            // W-load k row (0..15)
    int wc = (tid & 15) * 4;      // W-load col (0..60)

    float acc[4][4] = {};

    for (int k0 = 0; k0 < kin; k0 += BK) {
        float4 a = make_float4(0.f, 0.f, 0.f, 0.f);
        int arow = rowBase + lr;
        if (arow < n) a = *(const float4*)&A[(size_t)arow * kin + k0 + lc];
        As[lc + 0][lr] = a.x; As[lc + 1][lr] = a.y;
        As[lc + 2][lr] = a.z; As[lc + 3][lr] = a.w;

        float4 w = *(const float4*)&W[(size_t)(k0 + wr) * kout + colBase + wc];
        *(float4*)&Ws[wr][wc] = w;
        __syncthreads();

#pragma unroll
        for (int kk = 0; kk < BK; kk++) {
            float4 av = *(const float4*)&As[kk][ty * 4];
            float4 wv = *(const float4*)&Ws[kk][tx * 4];
            acc[0][0] += av.x * wv.x; acc[0][1] += av.x * wv.y; acc[0][2] += av.x * wv.z; acc[0][3] += av.x * wv.w;
            acc[1][0] += av.y * wv.x; acc[1][1] += av.y * wv.y; acc[1][2] += av.y * wv.z; acc[1][3] += av.y * wv.w;
            acc[2][0] += av.z * wv.x; acc[2][1] += av.z * wv.y; acc[2][2] += av.z * wv.z; acc[2][3] += av.z * wv.w;
            acc[3][0] += av.w * wv.x; acc[3][1] += av.w * wv.y; acc[3][2] += av.w * wv.z; acc[3][3] += av.w * wv.w;
        }
        __syncthreads();
    }

#pragma unroll
    for (int i = 0; i < 4; i++) {
        int row = rowBase + ty * 4 + i;
        if (row < n) {
            float4 v = make_float4(acc[i][0], acc[i][1], acc[i][2], acc[i][3]);
            *(float4*)&C[(size_t)row * kout + colBase + tx * 4] = v;
        }
    }
}

// ------------------- small GEMM for layer 2: kin=256, kout=16 ---------------
__global__ void gemm16(const float* __restrict__ A, const float* __restrict__ W,
                       float* __restrict__ C, int n) {
    __shared__ float As[16][256];
    __shared__ float Ws[256 * 16];
    int tid = threadIdx.x;        // 256
    int base = blockIdx.x * 16;

    // load W (4096 floats = 1024 float4)
    for (int i = tid; i < 1024; i += 256)
        ((float4*)Ws)[i] = ((const float4*)W)[i];
    // load 16 A rows
    for (int i = tid; i < 1024; i += 256) {
        int r = i >> 6, c4 = i & 63;
        float4 v = make_float4(0.f, 0.f, 0.f, 0.f);
        if (base + r < n) v = ((const float4*)(A + (size_t)(base + r) * 256))[c4];
        ((float4*)&As[r][0])[c4] = v;
    }
    __syncthreads();

    int ni = tid >> 4, oi = tid & 15;
    float acc = 0.f;
#pragma unroll 8
    for (int k = 0; k < 256; k++)
        acc += As[ni][k] * Ws[k * 16 + oi];
    if (base + ni < n) C[(size_t)(base + ni) * 16 + oi] = acc;
}

// ------------------------- el/er: one warp per node -------------------------
__global__ void eler_kernel(const float* __restrict__ feat, const float* __restrict__ al,
                            const float* __restrict__ ar, float* __restrict__ el,
                            float* __restrict__ er, int n, int H, int D) {
    int warp = (blockIdx.x * blockDim.x + threadIdx.x) >> 5;
    int lane = threadIdx.x & 31;
    if (warp >= n) return;
    const float* f = feat + (size_t)warp * H * D;
    for (int h = 0; h < H; h++) {
        float sl = 0.f, sr = 0.f;
        for (int d = lane; d < D; d += 32) {
            float v = f[h * D + d];
            sl += v * al[h * D + d];
            sr += v * ar[h * D + d];
        }
#pragma unroll
        for (int o = 16; o; o >>= 1) {
            sl += __shfl_xor_sync(0xffffffffu, sl, o);
            sr += __shfl_xor_sync(0xffffffffu, sr, o);
        }
        if (lane == 0) { el[warp * H + h] = sl; er[warp * H + h] = sr; }
    }
}

// ------------------------- init: out = bias bcast, s=0, mu=0 ----------------
__global__ void init_kernel(float* __restrict__ out, const float* __restrict__ b,
                            float* __restrict__ s, unsigned* __restrict__ mu,
                            int n, int HD, int H) {
    int idx = blockIdx.x * blockDim.x + threadIdx.x;
    if (idx < n * HD) out[idx] = b[idx % HD];
    if (idx < n * H) { s[idx] = 0.f; mu[idx] = 0u; }
}

// ------------------------- pass 1: logits + segment max ---------------------
__global__ void edge_logits(const int* __restrict__ src, const int* __restrict__ dst,
                            const float* __restrict__ el, const float* __restrict__ er,
                            float* __restrict__ e, unsigned* __restrict__ mu, int H) {
    int idx = blockIdx.x * blockDim.x + threadIdx.x;
    if (idx >= NE * H) return;
    int eid = idx / H, h = idx - eid * H;
    int s = src[eid], d = dst[eid];
    float x = el[s * H + h] + er[d * H + h];
    x = x > 0.f ? x : 0.2f * x;
    e[idx] = x;
    unsigned key = __float_as_uint(x);
    key = (key & 0x80000000u) ? ~key : (key | 0x80000000u);
    atomicMax(&mu[d * H + h], key);
}

__global__ void decode_max(const unsigned* __restrict__ mu, float* __restrict__ mf, int cnt) {
    int idx = blockIdx.x * blockDim.x + threadIdx.x;
    if (idx >= cnt) return;
    unsigned k = mu[idx];
    unsigned u = (k & 0x80000000u) ? (k & 0x7FFFFFFFu) : ~k;
    mf[idx] = __uint_as_float(u);
}

// ------------------------- pass 2: exp + segment sum ------------------------
__global__ void edge_expsum(const int* __restrict__ dst, float* __restrict__ e,
                            const float* __restrict__ mf, float* __restrict__ s, int H) {
    int idx = blockIdx.x * blockDim.x + threadIdx.x;
    if (idx >= NE * H) return;
    int eid = idx / H, h = idx - eid * H;
    int d = dst[eid];
    float v = expf(e[idx] - mf[d * H + h]);
    e[idx] = v;
    atomicAdd(&s[d * H + h], v);
}

// ------------------------- pass 3: weighted aggregate (H=4, D=64) -----------
__global__ void edge_aggregate256(const int* __restrict__ src, const int* __restrict__ dst,
                                  const float* __restrict__ feat, const float* __restrict__ e,
                                  const float* __restrict__ s, float* __restrict__ out) {
    int warp = (blockIdx.x * blockDim.x + threadIdx.x) >> 5;
    if (warp >= NE) return;
    int lane = threadIdx.x & 31;
    int sn = src[warp], dn = dst[warp];
    float aval = 0.f;
    if (lane < 4) aval = e[warp * 4 + lane] / s[dn * 4 + lane];
    const float4* fp = (const float4*)(feat + (size_t)sn * 256);
    float* op = out + (size_t)dn * 256;
#pragma unroll
    for (int it = 0; it < 2; it++) {
        int f4 = it * 32 + lane;          // float4 index 0..63
        int h = f4 >> 4;                  // 16 float4 per head
        float a = __shfl_sync(0xffffffffu, aval, h);
        float4 v = fp[f4];
        v.x *= a; v.y *= a; v.z *= a; v.w *= a;
        asm volatile("red.global.add.v4.f32 [%0], {%1,%2,%3,%4};"
                     :: "l"(op + f4 * 4), "f"(v.x), "f"(v.y), "f"(v.z), "f"(v.w)
                     : "memory");
    }
}

// ------------------------- pass 3 for layer 2 (H=1, D=16) -------------------
__global__ void edge_aggregate16(const int* __restrict__ src, const int* __restrict__ dst,
                                 const float* __restrict__ feat, const float* __restrict__ e,
                                 const float* __restrict__ s, float* __restrict__ out) {
    int idx = blockIdx.x * blockDim.x + threadIdx.x;
    if (idx >= NE * 4) return;
    int eid = idx >> 2, q = idx & 3;
    int sn = src[eid], dn = dst[eid];
    float a = e[eid] / s[dn];
    float4 v = ((const float4*)(feat + (size_t)sn * 16))[q];
    v.x *= a; v.y *= a; v.z *= a; v.w *= a;
    asm volatile("red.global.add.v4.f32 [%0], {%1,%2,%3,%4};"
                 :: "l"(out + (size_t)dn * 16 + q * 4), "f"(v.x), "f"(v.y), "f"(v.z), "f"(v.w)
                 : "memory");
}

// ---------------------------------------------------------------------------
extern "C" void kernel_launch(void* const* d_in, const int* in_sizes, int n_in,
                              void* d_out, int out_size) {
    const float* inputs = (const float*)d_in[0];
    const float* W0 = (const float*)d_in[1];
    const float* al0 = (const float*)d_in[2];
    const float* ar0 = (const float*)d_in[3];
    const float* b0 = (const float*)d_in[4];
    const float* W1 = (const float*)d_in[5];
    const float* al1 = (const float*)d_in[6];
    const float* ar1 = (const float*)d_in[7];
    const float* b1 = (const float*)d_in[8];
    const float* W2 = (const float*)d_in[9];
    const float* al2 = (const float*)d_in[10];
    const float* ar2 = (const float*)d_in[11];
    const float* b2 = (const float*)d_in[12];
    const int* src = (const int*)d_in[13];
    const int* dst = (const int*)d_in[14];

    float *feat, *h, *el, *er, *ebuf, *mf, *sbuf;
    unsigned* mu;
    cudaGetSymbolAddress((void**)&feat, g_feat);
    cudaGetSymbolAddress((void**)&h, g_h);
    cudaGetSymbolAddress((void**)&el, g_el);
    cudaGetSymbolAddress((void**)&er, g_er);
    cudaGetSymbolAddress((void**)&ebuf, g_e);
    cudaGetSymbolAddress((void**)&mu, g_mu);
    cudaGetSymbolAddress((void**)&mf, g_mf);
    cudaGetSymbolAddress((void**)&sbuf, g_s);

    dim3 gemmGrid(4, (NN + BM - 1) / BM);
    int elerBlocks = (NN * 32 + 255) / 256;
    int edgeBlocks4 = (NE * 4 + 255) / 256;
    int edgeBlocks1 = (NE + 255) / 256;
    int aggBlocks = (NE * 32 + 255) / 256;
    int initBlocks256 = (NN * 256 + 255) / 256;
    int initBlocks16 = (NN * 16 + 255) / 256;

    // ---------------- Layer 0: 128 -> (4,64) ----------------
    gemm_tiled<<<gemmGrid, 256>>>(inputs, W0, feat, NN, 128, 256);
    eler_kernel<<<elerBlocks, 256>>>(feat, al0, ar0, el, er, NN, 4, 64);
    init_kernel<<<initBlocks256, 256>>>(h, b0, sbuf, mu, NN, 256, 4);
    edge_logits<<<edgeBlocks4, 256>>>(src, dst, el, er, ebuf, mu, 4);
    decode_max<<<(NN * 4 + 255) / 256, 256>>>(mu, mf, NN * 4);
    edge_expsum<<<edgeBlocks4, 256>>>(dst, ebuf, mf, sbuf, 4);
    edge_aggregate256<<<aggBlocks, 256>>>(src, dst, feat, ebuf, sbuf, h);

    // ---------------- Layer 1: 256 -> (4,64) ----------------
    gemm_tiled<<<gemmGrid, 256>>>(h, W1, feat, NN, 256, 256);
    eler_kernel<<<elerBlocks, 256>>>(feat, al1, ar1, el, er, NN, 4, 64);
    init_kernel<<<initBlocks256, 256>>>(h, b1, sbuf, mu, NN, 256, 4);
    edge_logits<<<edgeBlocks4, 256>>>(src, dst, el, er, ebuf, mu, 4);
    decode_max<<<(NN * 4 + 255) / 256, 256>>>(mu, mf, NN * 4);
    edge_expsum<<<edgeBlocks4, 256>>>(dst, ebuf, mf, sbuf, 4);
    edge_aggregate256<<<aggBlocks, 256>>>(src, dst, feat, ebuf, sbuf, h);

    // ---------------- Layer 2: 256 -> (1,16), output logits ----------------
    float* out = (float*)d_out;
    gemm16<<<(NN + 15) / 16, 256>>>(h, W2, feat, NN);
    eler_kernel<<<elerBlocks, 256>>>(feat, al2, ar2, el, er, NN, 1, 16);
    init_kernel<<<initBlocks16, 256>>>(out, b2, sbuf, mu, NN, 16, 1);
    edge_logits<<<edgeBlocks1, 256>>>(src, dst, el, er, ebuf, mu, 1);
    decode_max<<<(NN + 255) / 256, 256>>>(mu, mf, NN);
    edge_expsum<<<edgeBlocks1, 256>>>(dst, ebuf, mf, sbuf, 1);
    edge_aggregate16<<<edgeBlocks4, 256>>>(src, dst, feat, ebuf, sbuf, out);
}

// round 3
// speedup vs baseline: 1.1560x; 1.1560x over previous
#include <cuda_runtime.h>
#include <cuda_bf16.h>
#include <cstdint>

#define NN 50000
#define NE 800000

// ------------------------- scratch (device globals) -------------------------
__device__ float    g_feat[NN * 256];
__device__ float    g_h[NN * 256];
__device__ float    g_el[NN * 4];
__device__ float    g_er[NN * 4];
__device__ float    g_e[NE * 4];
__device__ unsigned g_mu[NN * 4];
__device__ float    g_mf[NN * 4];
__device__ float    g_s[NN * 4];
__device__ __nv_bfloat16 g_Ahi[NN * 256];
__device__ __nv_bfloat16 g_Alo[NN * 256];
__device__ __nv_bfloat16 g_Whi[256 * 256];   // transposed: [kout=256, kin] K-major
__device__ __nv_bfloat16 g_Wlo[256 * 256];

__device__ __forceinline__ uint32_t smem_u32(const void* p) {
    uint32_t a;
    asm("{ .reg .u64 t; cvta.to.shared.u64 t, %1; cvt.u32.u64 %0, t; }" : "=r"(a) : "l"(p));
    return a;
}

// ------------------------- fp32 -> bf16 hi/lo converts ----------------------
__global__ void convA_kernel(const float* __restrict__ A, __nv_bfloat16* __restrict__ hi,
                             __nv_bfloat16* __restrict__ lo, int count4) {
    int i = blockIdx.x * blockDim.x + threadIdx.x;
    if (i >= count4) return;
    float4 v = ((const float4*)A)[i];
    __nv_bfloat16 h0 = __float2bfloat16(v.x), h1 = __float2bfloat16(v.y);
    __nv_bfloat16 h2 = __float2bfloat16(v.z), h3 = __float2bfloat16(v.w);
    __nv_bfloat16 l0 = __float2bfloat16(v.x - __bfloat162float(h0));
    __nv_bfloat16 l1 = __float2bfloat16(v.y - __bfloat162float(h1));
    __nv_bfloat16 l2 = __float2bfloat16(v.z - __bfloat162float(h2));
    __nv_bfloat16 l3 = __float2bfloat16(v.w - __bfloat162float(h3));
    __nv_bfloat162* ph = (__nv_bfloat162*)hi;
    __nv_bfloat162* pl = (__nv_bfloat162*)lo;
    ph[i * 2 + 0] = __nv_bfloat162(h0, h1);
    ph[i * 2 + 1] = __nv_bfloat162(h2, h3);
    pl[i * 2 + 0] = __nv_bfloat162(l0, l1);
    pl[i * 2 + 1] = __nv_bfloat162(l2, l3);
}

// W [kin, 256] -> Wt hi/lo [256, kin]
__global__ void convW_kernel(const float* __restrict__ W, __nv_bfloat16* __restrict__ thi,
                             __nv_bfloat16* __restrict__ tlo, int kin) {
    int i = blockIdx.x * blockDim.x + threadIdx.x;
    if (i >= kin * 256) return;
    int k = i >> 8, o = i & 255;
    float v = W[i];
    __nv_bfloat16 h = __float2bfloat16(v);
    thi[o * kin + k] = h;
    tlo[o * kin + k] = __float2bfloat16(v - __bfloat162float(h));
}

// ------------------- HMMA GEMM: C[n,256] = A[n,kin] @ Wt^T ------------------
// CTA tile 128(M) x 128(N), K-chunk 64 (one SW128 atom row). 256 thr = 8 warps,
// warp tile 64x32 = 4x4 m16n8k16 mma tiles. bf16 hi/lo split: 3 mmas / product.
#define SWZ(b) ((b) ^ (((b) >> 3) & 0x70))
#define HMMA_SMEM (4 * 128 * 64 * 2)   // Ahi, Alo, Whi, Wlo tiles = 64KB

__device__ __forceinline__ void mma16816(float* c, const uint32_t* a, const uint32_t* b) {
    asm volatile(
        "mma.sync.aligned.m16n8k16.row.col.f32.bf16.bf16.f32 "
        "{%0,%1,%2,%3}, {%4,%5,%6,%7}, {%8,%9}, {%0,%1,%2,%3};"
        : "+f"(c[0]), "+f"(c[1]), "+f"(c[2]), "+f"(c[3])
        : "r"(a[0]), "r"(a[1]), "r"(a[2]), "r"(a[3]), "r"(b[0]), "r"(b[1]));
}
__device__ __forceinline__ void ldsm4(uint32_t* r, uint32_t addr) {
    asm volatile("ldmatrix.sync.aligned.m8n8.x4.shared.b16 {%0,%1,%2,%3}, [%4];"
                 : "=r"(r[0]), "=r"(r[1]), "=r"(r[2]), "=r"(r[3]) : "r"(addr));
}

__global__ void __launch_bounds__(256, 1) hmma_gemm(
    const __nv_bfloat16* __restrict__ Ahi, const __nv_bfloat16* __restrict__ Alo,
    const __nv_bfloat16* __restrict__ Bhi, const __nv_bfloat16* __restrict__ Blo,
    float* __restrict__ C, int n, int kin)
{
    extern __shared__ char smem[];
    char* sAhi = smem;                    // 128 rows x 128B
    char* sAlo = smem + 16384;
    char* sWhi = smem + 32768;
    char* sWlo = smem + 49152;

    int tid = threadIdx.x, wid = tid >> 5, lane = tid & 31;
    int baseM = blockIdx.y * 128;
    int baseN = blockIdx.x * 128;
    int wm = wid >> 2, wn = wid & 3;     // warp tile: rows wm*64, cols wn*32

    float acc[4][4][4];
#pragma unroll
    for (int i = 0; i < 4; i++)
#pragma unroll
        for (int j = 0; j < 4; j++)
#pragma unroll
            for (int q = 0; q < 4; q++) acc[i][j][q] = 0.f;

    // precomputed ldmatrix lane address pieces
    int arow = wm * 64 + (lane & 15);          // + mi*16
    int ahalf16 = (lane >> 4) * 16;
    int brow = wn * 32 + ((lane >> 4) << 3) + (lane & 7);  // + p*16
    int bhalf16 = ((lane >> 3) & 1) * 16;

    uint32_t sb = smem_u32(smem);

    int nchunks = kin >> 6;
    for (int kc = 0; kc < nchunks; kc++) {
        // ---- load tiles: 1024 x 16B chunks per buffer ----
#pragma unroll
        for (int it = 0; it < 4; it++) {
            int c = it * 256 + tid;
            int row = c >> 3, cj = c & 7;
            uint32_t off = row * 128 + ((cj * 16) ^ ((row & 7) << 4));
            // A
            uint4 vh = make_uint4(0, 0, 0, 0), vl = make_uint4(0, 0, 0, 0);
            int gr = baseM + row;
            if (gr < n) {
                size_t gi = (size_t)gr * kin + kc * 64 + cj * 8;
                vh = *(const uint4*)(Ahi + gi);
                vl = *(const uint4*)(Alo + gi);
            }
            *(uint4*)(sAhi + off) = vh;
            *(uint4*)(sAlo + off) = vl;
            // W
            size_t wi = (size_t)(baseN + row) * kin + kc * 64 + cj * 8;
            *(uint4*)(sWhi + off) = *(const uint4*)(Bhi + wi);
            *(uint4*)(sWlo + off) = *(const uint4*)(Blo + wi);
        }
        __syncthreads();

#pragma unroll
        for (int s = 0; s < 4; s++) {       // k16 steps within the 64-chunk
            uint32_t ah[4][4], al[4][4], bh[2][4], bl[2][4];
#pragma unroll
            for (int mi = 0; mi < 4; mi++) {
                int r = arow + mi * 16;
                uint32_t off = r * 128 + ((s * 32 + ahalf16) ^ ((r & 7) << 4));
                ldsm4(ah[mi], sb + (uint32_t)(sAhi - smem) + off);
                ldsm4(al[mi], sb + (uint32_t)(sAlo - smem) + off);
            }
#pragma unroll
            for (int p = 0; p < 2; p++) {
                int r = brow + p * 16;
                uint32_t off = r * 128 + ((s * 32 + bhalf16) ^ ((r & 7) << 4));
                ldsm4(bh[p], sb + (uint32_t)(sWhi - smem) + off);
                ldsm4(bl[p], sb + (uint32_t)(sWlo - smem) + off);
            }
#pragma unroll
            for (int mi = 0; mi < 4; mi++)
#pragma unroll
                for (int p = 0; p < 2; p++)
#pragma unroll
                    for (int q = 0; q < 2; q++) {
                        int t = p * 2 + q;
                        mma16816(acc[mi][t], ah[mi], &bh[p][q * 2]);
                        mma16816(acc[mi][t], ah[mi], &bl[p][q * 2]);
                        mma16816(acc[mi][t], al[mi], &bh[p][q * 2]);
                    }
        }
        __syncthreads();
    }

    // ---- epilogue ----
    int g = lane >> 2, t4 = lane & 3;
#pragma unroll
    for (int mi = 0; mi < 4; mi++) {
        int r0 = baseM + wm * 64 + mi * 16 + g;
        int r1 = r0 + 8;
#pragma unroll
        for (int t = 0; t < 4; t++) {
            int col = baseN + wn * 32 + t * 8 + t4 * 2;
            if (r0 < n) *(float2*)(C + (size_t)r0 * 256 + col) = make_float2(acc[mi][t][0], acc[mi][t][1]);
            if (r1 < n) *(float2*)(C + (size_t)r1 * 256 + col) = make_float2(acc[mi][t][2], acc[mi][t][3]);
        }
    }
}

// ------------------- small GEMM for layer 2: kin=256, kout=16 ---------------
__global__ void gemm16(const float* __restrict__ A, const float* __restrict__ W,
                       float* __restrict__ C, int n) {
    __shared__ float As[16][256];
    __shared__ float Wt[16][260];      // transposed W, padded
    int tid = threadIdx.x;
    int base = blockIdx.x * 16;
    for (int i = tid; i < 4096; i += 256) {
        int k = i >> 4, oi = i & 15;
        Wt[oi][k] = W[i];
    }
    for (int i = tid; i < 1024; i += 256) {
        int r = i >> 6, c4 = i & 63;
        float4 v = make_float4(0.f, 0.f, 0.f, 0.f);
        if (base + r < n) v = ((const float4*)(A + (size_t)(base + r) * 256))[c4];
        ((float4*)&As[r][0])[c4] = v;
    }
    __syncthreads();
    int ni = tid >> 4, oi = tid & 15;
    float acc = 0.f;
#pragma unroll 16
    for (int k4 = 0; k4 < 64; k4++) {
        float4 a = ((const float4*)&As[ni][0])[k4];
        float4 w = *(const float4*)&Wt[oi][k4 * 4];
        acc += a.x * w.x + a.y * w.y + a.z * w.z + a.w * w.w;
    }
    if (base + ni < n) C[(size_t)(base + ni) * 16 + oi] = acc;
}

// ------------------------- el/er: one warp per node -------------------------
__global__ void eler_kernel(const float* __restrict__ feat, const float* __restrict__ al,
                            const float* __restrict__ ar, float* __restrict__ el,
                            float* __restrict__ er, int n, int H, int D) {
    int warp = (blockIdx.x * blockDim.x + threadIdx.x) >> 5;
    int lane = threadIdx.x & 31;
    if (warp >= n) return;
    const float* f = feat + (size_t)warp * H * D;
    for (int h = 0; h < H; h++) {
        float sl = 0.f, sr = 0.f;
        for (int d = lane; d < D; d += 32) {
            float v = f[h * D + d];
            sl += v * al[h * D + d];
            sr += v * ar[h * D + d];
        }
#pragma unroll
        for (int o = 16; o; o >>= 1) {
            sl += __shfl_xor_sync(0xffffffffu, sl, o);
            sr += __shfl_xor_sync(0xffffffffu, sr, o);
        }
        if (lane == 0) { el[warp * H + h] = sl; er[warp * H + h] = sr; }
    }
}

// ------------------------- init: out = bias bcast, s=0, mu=0 ----------------
__global__ void init_kernel(float* __restrict__ out, const float* __restrict__ b,
                            float* __restrict__ s, unsigned* __restrict__ mu,
                            int n, int HD, int H) {
    int idx = blockIdx.x * blockDim.x + threadIdx.x;
    if (idx < n * HD) out[idx] = b[idx % HD];
    if (idx < n * H) { s[idx] = 0.f; mu[idx] = 0u; }
}

// ------------------------- pass 1: logits + segment max ---------------------
__global__ void edge_logits(const int* __restrict__ src, const int* __restrict__ dst,
                            const float* __restrict__ el, const float* __restrict__ er,
                            float* __restrict__ e, unsigned* __restrict__ mu, int H) {
    int idx = blockIdx.x * blockDim.x + threadIdx.x;
    if (idx >= NE * H) return;
    int eid = idx / H, h = idx - eid * H;
    int s = src[eid], d = dst[eid];
    float x = el[s * H + h] + er[d * H + h];
    x = x > 0.f ? x : 0.2f * x;
    e[idx] = x;
    unsigned key = __float_as_uint(x);
    key = (key & 0x80000000u) ? ~key : (key | 0x80000000u);
    atomicMax(&mu[d * H + h], key);
}

__global__ void decode_max(const unsigned* __restrict__ mu, float* __restrict__ mf, int cnt) {
    int idx = blockIdx.x * blockDim.x + threadIdx.x;
    if (idx >= cnt) return;
    unsigned k = mu[idx];
    unsigned u = (k & 0x80000000u) ? (k & 0x7FFFFFFFu) : ~k;
    mf[idx] = __uint_as_float(u);
}

// ------------------------- pass 2: exp + segment sum ------------------------
__global__ void edge_expsum(const int* __restrict__ dst, float* __restrict__ e,
                            const float* __restrict__ mf, float* __restrict__ s, int H) {
    int idx = blockIdx.x * blockDim.x + threadIdx.x;
    if (idx >= NE * H) return;
    int eid = idx / H, h = idx - eid * H;
    int d = dst[eid];
    float v = expf(e[idx] - mf[d * H + h]);
    e[idx] = v;
    atomicAdd(&s[d * H + h], v);
}

// ------------------------- pass 3: weighted aggregate (H=4, D=64) -----------
__global__ void edge_aggregate256(const int* __restrict__ src, const int* __restrict__ dst,
                                  const float* __restrict__ feat, const float* __restrict__ e,
                                  const float* __restrict__ s, float* __restrict__ out) {
    int warp = (blockIdx.x * blockDim.x + threadIdx.x) >> 5;
    if (warp >= NE) return;
    int lane = threadIdx.x & 31;
    int sn = src[warp], dn = dst[warp];
    float aval = 0.f;
    if (lane < 4) aval = e[warp * 4 + lane] / s[dn * 4 + lane];
    const float4* fp = (const float4*)(feat + (size_t)sn * 256);
    float* op = out + (size_t)dn * 256;
#pragma unroll
    for (int it = 0; it < 2; it++) {
        int f4 = it * 32 + lane;
        int h = f4 >> 4;
        float a = __shfl_sync(0xffffffffu, aval, h);
        float4 v = fp[f4];
        v.x *= a; v.y *= a; v.z *= a; v.w *= a;
        asm volatile("red.global.add.v4.f32 [%0], {%1,%2,%3,%4};"
                     :: "l"(op + f4 * 4), "f"(v.x), "f"(v.y), "f"(v.z), "f"(v.w)
                     : "memory");
    }
}

// ------------------------- pass 3 for layer 2 (H=1, D=16) -------------------
__global__ void edge_aggregate16(const int* __restrict__ src, const int* __restrict__ dst,
                                 const float* __restrict__ feat, const float* __restrict__ e,
                                 const float* __restrict__ s, float* __restrict__ out) {
    int idx = blockIdx.x * blockDim.x + threadIdx.x;
    if (idx >= NE * 4) return;
    int eid = idx >> 2, q = idx & 3;
    int sn = src[eid], dn = dst[eid];
    float a = e[eid] / s[dn];
    float4 v = ((const float4*)(feat + (size_t)sn * 16))[q];
    v.x *= a; v.y *= a; v.z *= a; v.w *= a;
    asm volatile("red.global.add.v4.f32 [%0], {%1,%2,%3,%4};"
                 :: "l"(out + (size_t)dn * 16 + q * 4), "f"(v.x), "f"(v.y), "f"(v.z), "f"(v.w)
                 : "memory");
}

// ---------------------------------------------------------------------------
extern "C" void kernel_launch(void* const* d_in, const int* in_sizes, int n_in,
                              void* d_out, int out_size) {
    const float* inputs = (const float*)d_in[0];
    const float* W0 = (const float*)d_in[1];
    const float* al0 = (const float*)d_in[2];
    const float* ar0 = (const float*)d_in[3];
    const float* b0 = (const float*)d_in[4];
    const float* W1 = (const float*)d_in[5];
    const float* al1 = (const float*)d_in[6];
    const float* ar1 = (const float*)d_in[7];
    const float* b1 = (const float*)d_in[8];
    const float* W2 = (const float*)d_in[9];
    const float* al2 = (const float*)d_in[10];
    const float* ar2 = (const float*)d_in[11];
    const float* b2 = (const float*)d_in[12];
    const int* src = (const int*)d_in[13];
    const int* dst = (const int*)d_in[14];

    float *feat, *h, *el, *er, *ebuf, *mf, *sbuf;
    unsigned* mu;
    __nv_bfloat16 *Ahi, *Alo, *Whi, *Wlo;
    cudaGetSymbolAddress((void**)&feat, g_feat);
    cudaGetSymbolAddress((void**)&h, g_h);
    cudaGetSymbolAddress((void**)&el, g_el);
    cudaGetSymbolAddress((void**)&er, g_er);
    cudaGetSymbolAddress((void**)&ebuf, g_e);
    cudaGetSymbolAddress((void**)&mu, g_mu);
    cudaGetSymbolAddress((void**)&mf, g_mf);
    cudaGetSymbolAddress((void**)&sbuf, g_s);
    cudaGetSymbolAddress((void**)&Ahi, g_Ahi);
    cudaGetSymbolAddress((void**)&Alo, g_Alo);
    cudaGetSymbolAddress((void**)&Whi, g_Whi);
    cudaGetSymbolAddress((void**)&Wlo, g_Wlo);

    cudaFuncSetAttribute(hmma_gemm, cudaFuncAttributeMaxDynamicSharedMemorySize, HMMA_SMEM);

    int elerBlocks = (NN * 32 + 255) / 256;
    int edgeBlocks4 = (NE * 4 + 255) / 256;
    int edgeBlocks1 = (NE + 255) / 256;
    int aggBlocks = (NE * 32 + 255) / 256;
    int initBlocks256 = (NN * 256 + 255) / 256;
    int initBlocks16 = (NN * 16 + 255) / 256;
    dim3 mmaGrid(2, (NN + 127) / 128);

    // ---------------- Layer 0: 128 -> (4,64) ----------------
    convA_kernel<<<(NN * 128 / 4 + 255) / 256, 256>>>(inputs, Ahi, Alo, NN * 128 / 4);
    convW_kernel<<<(128 * 256 + 255) / 256, 256>>>(W0, Whi, Wlo, 128);
    hmma_gemm<<<mmaGrid, 256, HMMA_SMEM>>>(Ahi, Alo, Whi, Wlo, feat, NN, 128);
    eler_kernel<<<elerBlocks, 256>>>(feat, al0, ar0, el, er, NN, 4, 64);
    init_kernel<<<initBlocks256, 256>>>(h, b0, sbuf, mu, NN, 256, 4);
    edge_logits<<<edgeBlocks4, 256>>>(src, dst, el, er, ebuf, mu, 4);
    decode_max<<<(NN * 4 + 255) / 256, 256>>>(mu, mf, NN * 4);
    edge_expsum<<<edgeBlocks4, 256>>>(dst, ebuf, mf, sbuf, 4);
    edge_aggregate256<<<aggBlocks, 256>>>(src, dst, feat, ebuf, sbuf, h);

    // ---------------- Layer 1: 256 -> (4,64) ----------------
    convA_kernel<<<(NN * 256 / 4 + 255) / 256, 256>>>(h, Ahi, Alo, NN * 256 / 4);
    convW_kernel<<<(256 * 256 + 255) / 256, 256>>>(W1, Whi, Wlo, 256);
    hmma_gemm<<<mmaGrid, 256, HMMA_SMEM>>>(Ahi, Alo, Whi, Wlo, feat, NN, 256);
    eler_kernel<<<elerBlocks, 256>>>(feat, al1, ar1, el, er, NN, 4, 64);
    init_kernel<<<initBlocks256, 256>>>(h, b1, sbuf, mu, NN, 256, 4);
    edge_logits<<<edgeBlocks4, 256>>>(src, dst, el, er, ebuf, mu, 4);
    decode_max<<<(NN * 4 + 255) / 256, 256>>>(mu, mf, NN * 4);
    edge_expsum<<<edgeBlocks4, 256>>>(dst, ebuf, mf, sbuf, 4);
    edge_aggregate256<<<aggBlocks, 256>>>(src, dst, feat, ebuf, sbuf, h);

    // ---------------- Layer 2: 256 -> (1,16), output logits ----------------
    float* out = (float*)d_out;
    gemm16<<<(NN + 15) / 16, 256>>>(h, W2, feat, NN);
    eler_kernel<<<elerBlocks, 256>>>(feat, al2, ar2, el, er, NN, 1, 16);
    init_kernel<<<initBlocks16, 256>>>(out, b2, sbuf, mu, NN, 16, 1);
    edge_logits<<<edgeBlocks1, 256>>>(src, dst, el, er, ebuf, mu, 1);
    decode_max<<<(NN + 255) / 256, 256>>>(mu, mf, NN);
    edge_expsum<<<edgeBlocks1, 256>>>(dst, ebuf, mf, sbuf, 1);
    edge_aggregate16<<<edgeBlocks4, 256>>>(src, dst, feat, ebuf, sbuf, out);
}

// round 6
// speedup vs baseline: 1.8009x; 1.5578x over previous
#include <cuda_runtime.h>
#include <cuda_bf16.h>
#include <cstdint>

#define NN 50000
#define NE 800000

// ------------------------- scratch (device globals) -------------------------
__device__ float    g_feat[NN * 256];
__device__ float    g_h[NN * 256];
__device__ float    g_el[NN * 4];
__device__ float    g_er[NN * 4];
__device__ float    g_e[NE * 4];        // per-edge logits -> exp values (CSR order)
__device__ int      g_cnt[NN];
__device__ int      g_rp[NN + 1];       // CSR row_ptr by dst
__device__ int      g_cur[NN];
__device__ int      g_csrc[NE];         // src per CSR slot
__device__ __nv_bfloat16 g_Ahi[NN * 256];
__device__ __nv_bfloat16 g_Alo[NN * 256];
__device__ __nv_bfloat16 g_Whi[256 * 256];
__device__ __nv_bfloat16 g_Wlo[256 * 256];

__device__ __forceinline__ uint32_t smem_u32(const void* p) {
    uint32_t a;
    asm("{ .reg .u64 t; cvta.to.shared.u64 t, %1; cvt.u32.u64 %0, t; }" : "=r"(a) : "l"(p));
    return a;
}

// ------------------------- CSR build ----------------------------------------
__global__ void zero_cnt(int* cnt) {
    int i = blockIdx.x * blockDim.x + threadIdx.x;
    if (i < NN) cnt[i] = 0;
}
__global__ void hist_kernel(const int* __restrict__ dst, int* __restrict__ cnt) {
    int i = blockIdx.x * blockDim.x + threadIdx.x;
    if (i < NE) atomicAdd(&cnt[dst[i]], 1);
}
__global__ void scan_kernel(const int* __restrict__ cnt, int* __restrict__ rp, int* __restrict__ cur) {
    __shared__ int part[1024];
    int t = threadIdx.x;
    const int CH = (NN + 1023) / 1024;
    int beg = t * CH, end = beg + CH > NN ? NN : beg + CH;
    int s = 0;
    for (int i = beg; i < end; i++) s += cnt[i];
    part[t] = s;
    __syncthreads();
    for (int d = 1; d < 1024; d <<= 1) {
        int v = (t >= d) ? part[t - d] : 0;
        __syncthreads();
        part[t] += v;
        __syncthreads();
    }
    int off = (t > 0) ? part[t - 1] : 0;
    for (int i = beg; i < end; i++) { rp[i] = off; cur[i] = off; off += cnt[i]; }
    if (t == 0) rp[NN] = NE;
}
__global__ void scatter_kernel(const int* __restrict__ src, const int* __restrict__ dst,
                               int* __restrict__ cur, int* __restrict__ csrc) {
    int i = blockIdx.x * blockDim.x + threadIdx.x;
    if (i >= NE) return;
    int p = atomicAdd(&cur[dst[i]], 1);
    csrc[p] = src[i];
}

// ------------------------- fp32 -> bf16 hi/lo converts ----------------------
__global__ void convA_kernel(const float* __restrict__ A, __nv_bfloat16* __restrict__ hi,
                             __nv_bfloat16* __restrict__ lo, int count4) {
    int i = blockIdx.x * blockDim.x + threadIdx.x;
    if (i >= count4) return;
    float4 v = ((const float4*)A)[i];
    __nv_bfloat16 h0 = __float2bfloat16(v.x), h1 = __float2bfloat16(v.y);
    __nv_bfloat16 h2 = __float2bfloat16(v.z), h3 = __float2bfloat16(v.w);
    __nv_bfloat16 l0 = __float2bfloat16(v.x - __bfloat162float(h0));
    __nv_bfloat16 l1 = __float2bfloat16(v.y - __bfloat162float(h1));
    __nv_bfloat16 l2 = __float2bfloat16(v.z - __bfloat162float(h2));
    __nv_bfloat16 l3 = __float2bfloat16(v.w - __bfloat162float(h3));
    __nv_bfloat162* ph = (__nv_bfloat162*)hi;
    __nv_bfloat162* pl = (__nv_bfloat162*)lo;
    ph[i * 2 + 0] = __nv_bfloat162(h0, h1);
    ph[i * 2 + 1] = __nv_bfloat162(h2, h3);
    pl[i * 2 + 0] = __nv_bfloat162(l0, l1);
    pl[i * 2 + 1] = __nv_bfloat162(l2, l3);
}

__global__ void convW_kernel(const float* __restrict__ W, __nv_bfloat16* __restrict__ thi,
                             __nv_bfloat16* __restrict__ tlo, int kin) {
    int i = blockIdx.x * blockDim.x + threadIdx.x;
    if (i >= kin * 256) return;
    int k = i >> 8, o = i & 255;
    float v = W[i];
    __nv_bfloat16 h = __float2bfloat16(v);
    thi[o * kin + k] = h;
    tlo[o * kin + k] = __float2bfloat16(v - __bfloat162float(h));
}

// ------------------- HMMA GEMM (validated in R3) ----------------------------
#define HMMA_SMEM (4 * 128 * 64 * 2)

__device__ __forceinline__ void mma16816(float* c, const uint32_t* a, const uint32_t* b) {
    asm volatile(
        "mma.sync.aligned.m16n8k16.row.col.f32.bf16.bf16.f32 "
        "{%0,%1,%2,%3}, {%4,%5,%6,%7}, {%8,%9}, {%0,%1,%2,%3};"
        : "+f"(c[0]), "+f"(c[1]), "+f"(c[2]), "+f"(c[3])
        : "r"(a[0]), "r"(a[1]), "r"(a[2]), "r"(a[3]), "r"(b[0]), "r"(b[1]));
}
__device__ __forceinline__ void ldsm4(uint32_t* r, uint32_t addr) {
    asm volatile("ldmatrix.sync.aligned.m8n8.x4.shared.b16 {%0,%1,%2,%3}, [%4];"
                 : "=r"(r[0]), "=r"(r[1]), "=r"(r[2]), "=r"(r[3]) : "r"(addr));
}

__global__ void __launch_bounds__(256, 1) hmma_gemm(
    const __nv_bfloat16* __restrict__ Ahi, const __nv_bfloat16* __restrict__ Alo,
    const __nv_bfloat16* __restrict__ Bhi, const __nv_bfloat16* __restrict__ Blo,
    float* __restrict__ C, int n, int kin)
{
    extern __shared__ char smem[];
    char* sAhi = smem;
    char* sAlo = smem + 16384;
    char* sWhi = smem + 32768;
    char* sWlo = smem + 49152;

    int tid = threadIdx.x, wid = tid >> 5, lane = tid & 31;
    int baseM = blockIdx.y * 128;
    int baseN = blockIdx.x * 128;
    int wm = wid >> 2, wn = wid & 3;

    float acc[4][4][4];
#pragma unroll
    for (int i = 0; i < 4; i++)
#pragma unroll
        for (int j = 0; j < 4; j++)
#pragma unroll
            for (int q = 0; q < 4; q++) acc[i][j][q] = 0.f;

    int arow = wm * 64 + (lane & 15);
    int ahalf16 = (lane >> 4) * 16;
    int brow = wn * 32 + ((lane >> 4) << 3) + (lane & 7);
    int bhalf16 = ((lane >> 3) & 1) * 16;

    uint32_t sb = smem_u32(smem);

    int nchunks = kin >> 6;
    for (int kc = 0; kc < nchunks; kc++) {
#pragma unroll
        for (int it = 0; it < 4; it++) {
            int c = it * 256 + tid;
            int row = c >> 3, cj = c & 7;
            uint32_t off = row * 128 + ((cj * 16) ^ ((row & 7) << 4));
            uint4 vh = make_uint4(0, 0, 0, 0), vl = make_uint4(0, 0, 0, 0);
            int gr = baseM + row;
            if (gr < n) {
                size_t gi = (size_t)gr * kin + kc * 64 + cj * 8;
                vh = *(const uint4*)(Ahi + gi);
                vl = *(const uint4*)(Alo + gi);
            }
            *(uint4*)(sAhi + off) = vh;
            *(uint4*)(sAlo + off) = vl;
            size_t wi = (size_t)(baseN + row) * kin + kc * 64 + cj * 8;
            *(uint4*)(sWhi + off) = *(const uint4*)(Bhi + wi);
            *(uint4*)(sWlo + off) = *(const uint4*)(Blo + wi);
        }
        __syncthreads();

#pragma unroll
        for (int s = 0; s < 4; s++) {
            uint32_t ah[4][4], al[4][4], bh[2][4], bl[2][4];
#pragma unroll
            for (int mi = 0; mi < 4; mi++) {
                int r = arow + mi * 16;
                uint32_t off = r * 128 + ((s * 32 + ahalf16) ^ ((r & 7) << 4));
                ldsm4(ah[mi], sb + (uint32_t)(sAhi - smem) + off);
                ldsm4(al[mi], sb + (uint32_t)(sAlo - smem) + off);
            }
#pragma unroll
            for (int p = 0; p < 2; p++) {
                int r = brow + p * 16;
                uint32_t off = r * 128 + ((s * 32 + bhalf16) ^ ((r & 7) << 4));
                ldsm4(bh[p], sb + (uint32_t)(sWhi - smem) + off);
                ldsm4(bl[p], sb + (uint32_t)(sWlo - smem) + off);
            }
#pragma unroll
            for (int mi = 0; mi < 4; mi++)
#pragma unroll
                for (int p = 0; p < 2; p++)
#pragma unroll
                    for (int q = 0; q < 2; q++) {
                        int t = p * 2 + q;
                        mma16816(acc[mi][t], ah[mi], &bh[p][q * 2]);
                        mma16816(acc[mi][t], ah[mi], &bl[p][q * 2]);
                        mma16816(acc[mi][t], al[mi], &bh[p][q * 2]);
                    }
        }
        __syncthreads();
    }

    int g = lane >> 2, t4 = lane & 3;
#pragma unroll
    for (int mi = 0; mi < 4; mi++) {
        int r0 = baseM + wm * 64 + mi * 16 + g;
        int r1 = r0 + 8;
#pragma unroll
        for (int t = 0; t < 4; t++) {
            int col = baseN + wn * 32 + t * 8 + t4 * 2;
            if (r0 < n) *(float2*)(C + (size_t)r0 * 256 + col) = make_float2(acc[mi][t][0], acc[mi][t][1]);
            if (r1 < n) *(float2*)(C + (size_t)r1 * 256 + col) = make_float2(acc[mi][t][2], acc[mi][t][3]);
        }
    }
}

// ------------------- small GEMM for layer 2: kin=256, kout=16 ---------------
__global__ void gemm16(const float* __restrict__ A, const float* __restrict__ W,
                       float* __restrict__ C, int n) {
    __shared__ float As[16][256];
    __shared__ float Wt[16][260];
    int tid = threadIdx.x;
    int base = blockIdx.x * 16;
    for (int i = tid; i < 4096; i += 256) {
        int k = i >> 4, oi = i & 15;
        Wt[oi][k] = W[i];
    }
    for (int i = tid; i < 1024; i += 256) {
        int r = i >> 6, c4 = i & 63;
        float4 v = make_float4(0.f, 0.f, 0.f, 0.f);
        if (base + r < n) v = ((const float4*)(A + (size_t)(base + r) * 256))[c4];
        ((float4*)&As[r][0])[c4] = v;
    }
    __syncthreads();
    int ni = tid >> 4, oi = tid & 15;
    float acc = 0.f;
#pragma unroll 16
    for (int k4 = 0; k4 < 64; k4++) {
        float4 a = ((const float4*)&As[ni][0])[k4];
        float4 w = *(const float4*)&Wt[oi][k4 * 4];
        acc += a.x * w.x + a.y * w.y + a.z * w.z + a.w * w.w;
    }
    if (base + ni < n) C[(size_t)(base + ni) * 16 + oi] = acc;
}

// ------------------ eler for H=4,D=64: single-pass, 8-lane groups -----------
__global__ void eler4_kernel(const float* __restrict__ feat, const float* __restrict__ al,
                             const float* __restrict__ ar, float* __restrict__ el,
                             float* __restrict__ er) {
    int warp = (blockIdx.x * blockDim.x + threadIdx.x) >> 5;
    int lane = threadIdx.x & 31;
    if (warp >= NN) return;
    const float4* fp = (const float4*)(feat + (size_t)warp * 256 + lane * 8);
    const float4* ap = (const float4*)(al + lane * 8);
    const float4* rp = (const float4*)(ar + lane * 8);
    float4 f0 = fp[0], f1 = fp[1];
    float4 a0 = ap[0], a1 = ap[1];
    float4 r0 = rp[0], r1 = rp[1];
    float sl = f0.x * a0.x + f0.y * a0.y + f0.z * a0.z + f0.w * a0.w
             + f1.x * a1.x + f1.y * a1.y + f1.z * a1.z + f1.w * a1.w;
    float sr = f0.x * r0.x + f0.y * r0.y + f0.z * r0.z + f0.w * r0.w
             + f1.x * r1.x + f1.y * r1.y + f1.z * r1.z + f1.w * r1.w;
#pragma unroll
    for (int o = 4; o; o >>= 1) {
        sl += __shfl_xor_sync(0xffffffffu, sl, o);
        sr += __shfl_xor_sync(0xffffffffu, sr, o);
    }
    if ((lane & 7) == 0) {
        el[warp * 4 + (lane >> 3)] = sl;
        er[warp * 4 + (lane >> 3)] = sr;
    }
}

// ------------------ eler for H=1,D=16: thread per node ----------------------
__global__ void eler1_kernel(const float* __restrict__ feat, const float* __restrict__ al,
                             const float* __restrict__ ar, float* __restrict__ el,
                             float* __restrict__ er) {
    int n = blockIdx.x * blockDim.x + threadIdx.x;
    if (n >= NN) return;
    const float4* fp = (const float4*)(feat + (size_t)n * 16);
    float sl = 0.f, sr = 0.f;
#pragma unroll
    for (int q = 0; q < 4; q++) {
        float4 f = fp[q];
        float4 a = ((const float4*)al)[q];
        float4 r = ((const float4*)ar)[q];
        sl += f.x * a.x + f.y * a.y + f.z * a.z + f.w * a.w;
        sr += f.x * r.x + f.y * r.y + f.z * r.z + f.w * r.w;
    }
    el[n] = sl; er[n] = sr;
}

// -------- fused softmax + aggregate, H=4, D=64: one warp per dst node -------
// OUT_BF16=1: write hi/lo bf16 split (next layer's GEMM A operand) instead of fp32.
template <int OUT_BF16>
__global__ void __launch_bounds__(256) gat_fused4(
    const int* __restrict__ rp, const int* __restrict__ cs,
    const float* __restrict__ el, const float* __restrict__ er,
    const float* __restrict__ feat, const float* __restrict__ bias,
    float* __restrict__ ebuf, float* __restrict__ outf,
    __nv_bfloat16* __restrict__ outhi, __nv_bfloat16* __restrict__ outlo)
{
    int warp = (blockIdx.x * blockDim.x + threadIdx.x) >> 5;
    int lane = threadIdx.x & 31;
    if (warp >= NN) return;
    int s0 = rp[warp], s1 = rp[warp + 1];

    float4 er4 = *(const float4*)&er[warp * 4];

    // pass A: logits + max
    float m0 = -1e30f, m1 = -1e30f, m2 = -1e30f, m3 = -1e30f;
    for (int i = s0 + lane; i < s1; i += 32) {
        int sn = cs[i];
        float4 lv = *(const float4*)&el[sn * 4];
        lv.x += er4.x; lv.y += er4.y; lv.z += er4.z; lv.w += er4.w;
        lv.x = lv.x > 0.f ? lv.x : 0.2f * lv.x;
        lv.y = lv.y > 0.f ? lv.y : 0.2f * lv.y;
        lv.z = lv.z > 0.f ? lv.z : 0.2f * lv.z;
        lv.w = lv.w > 0.f ? lv.w : 0.2f * lv.w;
        *(float4*)&ebuf[i * 4] = lv;
        m0 = fmaxf(m0, lv.x); m1 = fmaxf(m1, lv.y);
        m2 = fmaxf(m2, lv.z); m3 = fmaxf(m3, lv.w);
    }
#pragma unroll
    for (int o = 16; o; o >>= 1) {
        m0 = fmaxf(m0, __shfl_xor_sync(0xffffffffu, m0, o));
        m1 = fmaxf(m1, __shfl_xor_sync(0xffffffffu, m1, o));
        m2 = fmaxf(m2, __shfl_xor_sync(0xffffffffu, m2, o));
        m3 = fmaxf(m3, __shfl_xor_sync(0xffffffffu, m3, o));
    }

    // pass B: exp + sum
    float t0 = 0.f, t1 = 0.f, t2 = 0.f, t3 = 0.f;
    for (int i = s0 + lane; i < s1; i += 32) {
        float4 v = *(const float4*)&ebuf[i * 4];
        v.x = __expf(v.x - m0); v.y = __expf(v.y - m1);
        v.z = __expf(v.z - m2); v.w = __expf(v.w - m3);
        *(float4*)&ebuf[i * 4] = v;
        t0 += v.x; t1 += v.y; t2 += v.z; t3 += v.w;
    }
#pragma unroll
    for (int o = 16; o; o >>= 1) {
        t0 += __shfl_xor_sync(0xffffffffu, t0, o);
        t1 += __shfl_xor_sync(0xffffffffu, t1, o);
        t2 += __shfl_xor_sync(0xffffffffu, t2, o);
        t3 += __shfl_xor_sync(0xffffffffu, t3, o);
    }

    int hl = lane >> 3;
    float sv = hl == 0 ? t0 : hl == 1 ? t1 : hl == 2 ? t2 : t3;
    float inv = 1.f / sv;

    // pass C: gather-aggregate into registers
    float a0 = 0.f, a1 = 0.f, a2 = 0.f, a3 = 0.f, a4 = 0.f, a5 = 0.f, a6 = 0.f, a7 = 0.f;
    for (int i = s0; i < s1; i++) {
        int sn = cs[i];
        float a = ebuf[i * 4 + hl] * inv;
        const float4* fp = (const float4*)(feat + (size_t)sn * 256 + lane * 8);
        float4 v0 = fp[0], v1 = fp[1];
        a0 += a * v0.x; a1 += a * v0.y; a2 += a * v0.z; a3 += a * v0.w;
        a4 += a * v1.x; a5 += a * v1.y; a6 += a * v1.z; a7 += a * v1.w;
    }
    const float4* bp = (const float4*)(bias + lane * 8);
    float4 b0 = bp[0], b1 = bp[1];
    float r[8] = { a0 + b0.x, a1 + b0.y, a2 + b0.z, a3 + b0.w,
                   a4 + b1.x, a5 + b1.y, a6 + b1.z, a7 + b1.w };
    if (OUT_BF16) {
        __nv_bfloat16 hi[8], lo[8];
#pragma unroll
        for (int q = 0; q < 8; q++) {
            hi[q] = __float2bfloat16(r[q]);
            lo[q] = __float2bfloat16(r[q] - __bfloat162float(hi[q]));
        }
        *(uint4*)(outhi + (size_t)warp * 256 + lane * 8) = *(const uint4*)hi;
        *(uint4*)(outlo + (size_t)warp * 256 + lane * 8) = *(const uint4*)lo;
    } else {
        float4* op = (float4*)(outf + (size_t)warp * 256 + lane * 8);
        op[0] = make_float4(r[0], r[1], r[2], r[3]);
        op[1] = make_float4(r[4], r[5], r[6], r[7]);
    }
}

// -------- fused softmax + aggregate, H=1, D=16: one warp per dst node -------
__global__ void __launch_bounds__(256) gat_fused1(
    const int* __restrict__ rp, const int* __restrict__ cs,
    const float* __restrict__ el, const float* __restrict__ er,
    const float* __restrict__ feat, const float* __restrict__ bias,
    float* __restrict__ ebuf, float* __restrict__ out)
{
    int warp = (blockIdx.x * blockDim.x + threadIdx.x) >> 5;
    int lane = threadIdx.x & 31;
    if (warp >= NN) return;
    int s0 = rp[warp], s1 = rp[warp + 1];
    float erv = er[warp];

    float m = -1e30f;
    for (int i = s0 + lane; i < s1; i += 32) {
        float x = el[cs[i]] + erv;
        x = x > 0.f ? x : 0.2f * x;
        ebuf[i] = x;
        m = fmaxf(m, x);
    }
#pragma unroll
    for (int o = 16; o; o >>= 1) m = fmaxf(m, __shfl_xor_sync(0xffffffffu, m, o));

    float t = 0.f;
    for (int i = s0 + lane; i < s1; i += 32) {
        float v = __expf(ebuf[i] - m);
        ebuf[i] = v;
        t += v;
    }
#pragma unroll
    for (int o = 16; o; o >>= 1) t += __shfl_xor_sync(0xffffffffu, t, o);
    float inv = 1.f / t;

    int half = lane >> 4, dk = lane & 15;
    float acc = 0.f;
    for (int i = s0 + half; i < s1; i += 2) {
        int sn = cs[i];
        float a = ebuf[i] * inv;
        acc += a * feat[(size_t)sn * 16 + dk];
    }
    acc += __shfl_xor_sync(0xffffffffu, acc, 16);
    if (lane < 16) out[(size_t)warp * 16 + lane] = acc + bias[lane];
}

// ---------------------------------------------------------------------------
extern "C" void kernel_launch(void* const* d_in, const int* in_sizes, int n_in,
                              void* d_out, int out_size) {
    const float* inputs = (const float*)d_in[0];
    const float* W0 = (const float*)d_in[1];
    const float* al0 = (const float*)d_in[2];
    const float* ar0 = (const float*)d_in[3];
    const float* b0 = (const float*)d_in[4];
    const float* W1 = (const float*)d_in[5];
    const float* al1 = (const float*)d_in[6];
    const float* ar1 = (const float*)d_in[7];
    const float* b1 = (const float*)d_in[8];
    const float* W2 = (const float*)d_in[9];
    const float* al2 = (const float*)d_in[10];
    const float* ar2 = (const float*)d_in[11];
    const float* b2 = (const float*)d_in[12];
    const int* src = (const int*)d_in[13];
    const int* dst = (const int*)d_in[14];

    float *feat, *h, *el, *er, *ebuf;
    int *cnt, *rpp, *cur, *csrc;
    __nv_bfloat16 *Ahi, *Alo, *Whi, *Wlo;
    cudaGetSymbolAddress((void**)&feat, g_feat);
    cudaGetSymbolAddress((void**)&h, g_h);
    cudaGetSymbolAddress((void**)&el, g_el);
    cudaGetSymbolAddress((void**)&er, g_er);
    cudaGetSymbolAddress((void**)&ebuf, g_e);
    cudaGetSymbolAddress((void**)&cnt, g_cnt);
    cudaGetSymbolAddress((void**)&rpp, g_rp);
    cudaGetSymbolAddress((void**)&cur, g_cur);
    cudaGetSymbolAddress((void**)&csrc, g_csrc);
    cudaGetSymbolAddress((void**)&Ahi, g_Ahi);
    cudaGetSymbolAddress((void**)&Alo, g_Alo);
    cudaGetSymbolAddress((void**)&Whi, g_Whi);
    cudaGetSymbolAddress((void**)&Wlo, g_Wlo);

    cudaFuncSetAttribute(hmma_gemm, cudaFuncAttributeMaxDynamicSharedMemorySize, HMMA_SMEM);

    int warpBlocks = (NN * 32 + 255) / 256;
    dim3 mmaGrid(2, (NN + 127) / 128);

    // ---------------- CSR build (graph is static across layers) ------------
    zero_cnt<<<(NN + 255) / 256, 256>>>(cnt);
    hist_kernel<<<(NE + 255) / 256, 256>>>(dst, cnt);
    scan_kernel<<<1, 1024>>>(cnt, rpp, cur);
    scatter_kernel<<<(NE + 255) / 256, 256>>>(src, dst, cur, csrc);

    // ---------------- Layer 0: 128 -> (4,64) ----------------
    convA_kernel<<<(NN * 128 / 4 + 255) / 256, 256>>>(inputs, Ahi, Alo, NN * 128 / 4);
    convW_kernel<<<(128 * 256 + 255) / 256, 256>>>(W0, Whi, Wlo, 128);
    hmma_gemm<<<mmaGrid, 256, HMMA_SMEM>>>(Ahi, Alo, Whi, Wlo, feat, NN, 128);
    eler4_kernel<<<warpBlocks, 256>>>(feat, al0, ar0, el, er);
    // writes bf16 hi/lo directly (A operand of layer-1 GEMM)
    gat_fused4<1><<<warpBlocks, 256>>>(rpp, csrc, el, er, feat, b0, ebuf,
                                       nullptr, Ahi, Alo);

    // ---------------- Layer 1: 256 -> (4,64) ----------------
    convW_kernel<<<(256 * 256 + 255) / 256, 256>>>(W1, Whi, Wlo, 256);
    hmma_gemm<<<mmaGrid, 256, HMMA_SMEM>>>(Ahi, Alo, Whi, Wlo, feat, NN, 256);
    eler4_kernel<<<warpBlocks, 256>>>(feat, al1, ar1, el, er);
    // writes fp32 (consumed by fp32 gemm16)
    gat_fused4<0><<<warpBlocks, 256>>>(rpp, csrc, el, er, feat, b1, ebuf,
                                       h, nullptr, nullptr);

    // ---------------- Layer 2: 256 -> (1,16), output logits ----------------
    float* out = (float*)d_out;
    gemm16<<<(NN + 15) / 16, 256>>>(h, W2, feat, NN);
    eler1_kernel<<<(NN + 255) / 256, 256>>>(feat, al2, ar2, el, er);
    gat_fused1<<<warpBlocks, 256>>>(rpp, csrc, el, er, feat, b2, ebuf, out);
}

// round 7
// speedup vs baseline: 1.9927x; 1.1065x over previous
#include <cuda_runtime.h>
#include <cuda_bf16.h>
#include <cstdint>

#define NN 50000
#define NE 800000

// ------------------------- scratch (device globals) -------------------------
__device__ float    g_feat[NN * 256];
__device__ float    g_h[NN * 256];
__device__ float    g_el[NN * 4];
__device__ float    g_er[NN * 4];
__device__ float    g_e[NE * 4];        // per-edge exp values (CSR order)
__device__ int      g_cnt[NN];
__device__ int      g_rp[NN + 1];       // CSR row_ptr by dst
__device__ int      g_cur[NN];
__device__ int      g_csrc[NE];         // src per CSR slot
__device__ __nv_bfloat16 g_Ahi[NN * 256];
__device__ __nv_bfloat16 g_Alo[NN * 256];
__device__ __nv_bfloat16 g_Whi[256 * 256];
__device__ __nv_bfloat16 g_Wlo[256 * 256];

__device__ __forceinline__ uint32_t smem_u32(const void* p) {
    uint32_t a;
    asm("{ .reg .u64 t; cvta.to.shared.u64 t, %1; cvt.u32.u64 %0, t; }" : "=r"(a) : "l"(p));
    return a;
}
__device__ __forceinline__ void cpa16(uint32_t s, const void* g) {
    asm volatile("cp.async.cg.shared.global [%0], [%1], 16;"
                 :: "r"(s), "l"(__cvta_generic_to_global(g)));
}

// ------------------------- CSR build ----------------------------------------
__global__ void zero_cnt(int* cnt) {
    int i = blockIdx.x * blockDim.x + threadIdx.x;
    if (i < NN) cnt[i] = 0;
}
__global__ void hist_kernel(const int* __restrict__ dst, int* __restrict__ cnt) {
    int i = blockIdx.x * blockDim.x + threadIdx.x;
    if (i < NE) atomicAdd(&cnt[dst[i]], 1);
}
__global__ void scan_kernel(const int* __restrict__ cnt, int* __restrict__ rp, int* __restrict__ cur) {
    __shared__ int part[1024];
    int t = threadIdx.x;
    const int CH = (NN + 1023) / 1024;
    int beg = t * CH, end = beg + CH > NN ? NN : beg + CH;
    int s = 0;
    for (int i = beg; i < end; i++) s += cnt[i];
    part[t] = s;
    __syncthreads();
    for (int d = 1; d < 1024; d <<= 1) {
        int v = (t >= d) ? part[t - d] : 0;
        __syncthreads();
        part[t] += v;
        __syncthreads();
    }
    int off = (t > 0) ? part[t - 1] : 0;
    for (int i = beg; i < end; i++) { rp[i] = off; cur[i] = off; off += cnt[i]; }
    if (t == 0) rp[NN] = NE;
}
__global__ void scatter_kernel(const int* __restrict__ src, const int* __restrict__ dst,
                               int* __restrict__ cur, int* __restrict__ csrc) {
    int i = blockIdx.x * blockDim.x + threadIdx.x;
    if (i >= NE) return;
    int p = atomicAdd(&cur[dst[i]], 1);
    csrc[p] = src[i];
}

// ------------------------- fp32 -> bf16 hi/lo converts ----------------------
__global__ void convA_kernel(const float* __restrict__ A, __nv_bfloat16* __restrict__ hi,
                             __nv_bfloat16* __restrict__ lo, int count4) {
    int i = blockIdx.x * blockDim.x + threadIdx.x;
    if (i >= count4) return;
    float4 v = ((const float4*)A)[i];
    __nv_bfloat16 h0 = __float2bfloat16(v.x), h1 = __float2bfloat16(v.y);
    __nv_bfloat16 h2 = __float2bfloat16(v.z), h3 = __float2bfloat16(v.w);
    __nv_bfloat16 l0 = __float2bfloat16(v.x - __bfloat162float(h0));
    __nv_bfloat16 l1 = __float2bfloat16(v.y - __bfloat162float(h1));
    __nv_bfloat16 l2 = __float2bfloat16(v.z - __bfloat162float(h2));
    __nv_bfloat16 l3 = __float2bfloat16(v.w - __bfloat162float(h3));
    __nv_bfloat162* ph = (__nv_bfloat162*)hi;
    __nv_bfloat162* pl = (__nv_bfloat162*)lo;
    ph[i * 2 + 0] = __nv_bfloat162(h0, h1);
    ph[i * 2 + 1] = __nv_bfloat162(h2, h3);
    pl[i * 2 + 0] = __nv_bfloat162(l0, l1);
    pl[i * 2 + 1] = __nv_bfloat162(l2, l3);
}

__global__ void convW_kernel(const float* __restrict__ W, __nv_bfloat16* __restrict__ thi,
                             __nv_bfloat16* __restrict__ tlo, int kin) {
    int i = blockIdx.x * blockDim.x + threadIdx.x;
    if (i >= kin * 256) return;
    int k = i >> 8, o = i & 255;
    float v = W[i];
    __nv_bfloat16 h = __float2bfloat16(v);
    thi[o * kin + k] = h;
    tlo[o * kin + k] = __float2bfloat16(v - __bfloat162float(h));
}

__global__ void zero_eler(float* __restrict__ el, float* __restrict__ er) {
    int i = blockIdx.x * blockDim.x + threadIdx.x;
    if (i < NN * 4) { el[i] = 0.f; er[i] = 0.f; }
}

// ------- HMMA GEMM, cp.async double-buffered, fused el/er epilogue ----------
#define HMMA_STAGE 65536
#define HMMA_SMEM  (2 * HMMA_STAGE)

__device__ __forceinline__ void mma16816(float* c, const uint32_t* a, const uint32_t* b) {
    asm volatile(
        "mma.sync.aligned.m16n8k16.row.col.f32.bf16.bf16.f32 "
        "{%0,%1,%2,%3}, {%4,%5,%6,%7}, {%8,%9}, {%0,%1,%2,%3};"
        : "+f"(c[0]), "+f"(c[1]), "+f"(c[2]), "+f"(c[3])
        : "r"(a[0]), "r"(a[1]), "r"(a[2]), "r"(a[3]), "r"(b[0]), "r"(b[1]));
}
__device__ __forceinline__ void ldsm4(uint32_t* r, uint32_t addr) {
    asm volatile("ldmatrix.sync.aligned.m8n8.x4.shared.b16 {%0,%1,%2,%3}, [%4];"
                 : "=r"(r[0]), "=r"(r[1]), "=r"(r[2]), "=r"(r[3]) : "r"(addr));
}

__global__ void __launch_bounds__(256, 1) hmma_gemm(
    const __nv_bfloat16* __restrict__ Ahi, const __nv_bfloat16* __restrict__ Alo,
    const __nv_bfloat16* __restrict__ Bhi, const __nv_bfloat16* __restrict__ Blo,
    float* __restrict__ C, int n, int kin,
    const float* __restrict__ alv, const float* __restrict__ arv,
    float* __restrict__ elo, float* __restrict__ ero)
{
    extern __shared__ char smem[];
    int tid = threadIdx.x, wid = tid >> 5, lane = tid & 31;
    int baseM = blockIdx.y * 128;
    int baseN = blockIdx.x * 128;
    int wm = wid >> 2, wn = wid & 3;

    float acc[4][4][4];
#pragma unroll
    for (int i = 0; i < 4; i++)
#pragma unroll
        for (int j = 0; j < 4; j++)
#pragma unroll
            for (int q = 0; q < 4; q++) acc[i][j][q] = 0.f;

    int arow = wm * 64 + (lane & 15);
    int ahalf16 = (lane >> 4) * 16;
    int brow = wn * 32 + ((lane >> 4) << 3) + (lane & 7);
    int bhalf16 = ((lane >> 3) & 1) * 16;

    uint32_t sb = smem_u32(smem);
    int nchunks = kin >> 6;

    auto load_chunk = [&](int kc, int stg) {
        uint32_t base = sb + stg * HMMA_STAGE;
#pragma unroll
        for (int it = 0; it < 4; it++) {
            int c = it * 256 + tid;
            int row = c >> 3, cj = c & 7;
            uint32_t off = row * 128 + ((cj * 16) ^ ((row & 7) << 4));
            int gr = baseM + row;
            if (gr < n) {
                size_t gi = (size_t)gr * kin + kc * 64 + cj * 8;
                cpa16(base + off, Ahi + gi);
                cpa16(base + 16384 + off, Alo + gi);
            } else {
                *(uint4*)(smem + stg * HMMA_STAGE + off) = make_uint4(0, 0, 0, 0);
                *(uint4*)(smem + stg * HMMA_STAGE + 16384 + off) = make_uint4(0, 0, 0, 0);
            }
            size_t wi = (size_t)(baseN + row) * kin + kc * 64 + cj * 8;
            cpa16(base + 32768 + off, Bhi + wi);
            cpa16(base + 49152 + off, Blo + wi);
        }
        asm volatile("cp.async.commit_group;" ::: "memory");
    };

    load_chunk(0, 0);
    for (int kc = 0; kc < nchunks; kc++) {
        if (kc + 1 < nchunks) {
            load_chunk(kc + 1, (kc + 1) & 1);
            asm volatile("cp.async.wait_group 1;" ::: "memory");
        } else {
            asm volatile("cp.async.wait_group 0;" ::: "memory");
        }
        __syncthreads();

        uint32_t sA  = sb + (kc & 1) * HMMA_STAGE;
        uint32_t sAl = sA + 16384;
        uint32_t sW  = sA + 32768;
        uint32_t sWl = sA + 49152;
#pragma unroll
        for (int s = 0; s < 4; s++) {
            uint32_t ah[4][4], al_[4][4], bh[2][4], bl[2][4];
#pragma unroll
            for (int mi = 0; mi < 4; mi++) {
                int r = arow + mi * 16;
                uint32_t off = r * 128 + ((s * 32 + ahalf16) ^ ((r & 7) << 4));
                ldsm4(ah[mi], sA + off);
                ldsm4(al_[mi], sAl + off);
            }
#pragma unroll
            for (int p = 0; p < 2; p++) {
                int r = brow + p * 16;
                uint32_t off = r * 128 + ((s * 32 + bhalf16) ^ ((r & 7) << 4));
                ldsm4(bh[p], sW + off);
                ldsm4(bl[p], sWl + off);
            }
#pragma unroll
            for (int mi = 0; mi < 4; mi++)
#pragma unroll
                for (int p = 0; p < 2; p++)
#pragma unroll
                    for (int q = 0; q < 2; q++) {
                        int t = p * 2 + q;
                        mma16816(acc[mi][t], ah[mi], &bh[p][q * 2]);
                        mma16816(acc[mi][t], ah[mi], &bl[p][q * 2]);
                        mma16816(acc[mi][t], al_[mi], &bh[p][q * 2]);
                    }
        }
        __syncthreads();
    }

    int g = lane >> 2, t4 = lane & 3;

    // ---- write C ----
#pragma unroll
    for (int mi = 0; mi < 4; mi++) {
        int r0 = baseM + wm * 64 + mi * 16 + g;
        int r1 = r0 + 8;
#pragma unroll
        for (int t = 0; t < 4; t++) {
            int col = baseN + wn * 32 + t * 8 + t4 * 2;
            if (r0 < n) *(float2*)(C + (size_t)r0 * 256 + col) = make_float2(acc[mi][t][0], acc[mi][t][1]);
            if (r1 < n) *(float2*)(C + (size_t)r1 * 256 + col) = make_float2(acc[mi][t][2], acc[mi][t][3]);
        }
    }

    // ---- fused el/er epilogue: this warp's cols are all in one head ----
    int hh = (baseN + wn * 32) >> 6;
    float av[4][2], rv[4][2];
#pragma unroll
    for (int t = 0; t < 4; t++) {
        int col = baseN + wn * 32 + t * 8 + t4 * 2;
        av[t][0] = alv[col]; av[t][1] = alv[col + 1];
        rv[t][0] = arv[col]; rv[t][1] = arv[col + 1];
    }
#pragma unroll
    for (int mi = 0; mi < 4; mi++) {
        float e0 = 0.f, e1 = 0.f, f0 = 0.f, f1 = 0.f;
#pragma unroll
        for (int t = 0; t < 4; t++) {
            e0 += acc[mi][t][0] * av[t][0] + acc[mi][t][1] * av[t][1];
            e1 += acc[mi][t][2] * av[t][0] + acc[mi][t][3] * av[t][1];
            f0 += acc[mi][t][0] * rv[t][0] + acc[mi][t][1] * rv[t][1];
            f1 += acc[mi][t][2] * rv[t][0] + acc[mi][t][3] * rv[t][1];
        }
#pragma unroll
        for (int o = 1; o <= 2; o <<= 1) {
            e0 += __shfl_xor_sync(0xffffffffu, e0, o);
            e1 += __shfl_xor_sync(0xffffffffu, e1, o);
            f0 += __shfl_xor_sync(0xffffffffu, f0, o);
            f1 += __shfl_xor_sync(0xffffffffu, f1, o);
        }
        if (t4 == 0) {
            int r0 = baseM + wm * 64 + mi * 16 + g;
            int r1 = r0 + 8;
            if (r0 < n) { atomicAdd(&elo[r0 * 4 + hh], e0); atomicAdd(&ero[r0 * 4 + hh], f0); }
            if (r1 < n) { atomicAdd(&elo[r1 * 4 + hh], e1); atomicAdd(&ero[r1 * 4 + hh], f1); }
        }
    }
}

// ------------------- small GEMM for layer 2: kin=256, kout=16 ---------------
__global__ void gemm16(const float* __restrict__ A, const float* __restrict__ W,
                       float* __restrict__ C, int n) {
    __shared__ float As[16][256];
    __shared__ float Wt[16][260];
    int tid = threadIdx.x;
    int base = blockIdx.x * 16;
    for (int i = tid; i < 4096; i += 256) {
        int k = i >> 4, oi = i & 15;
        Wt[oi][k] = W[i];
    }
    for (int i = tid; i < 1024; i += 256) {
        int r = i >> 6, c4 = i & 63;
        float4 v = make_float4(0.f, 0.f, 0.f, 0.f);
        if (base + r < n) v = ((const float4*)(A + (size_t)(base + r) * 256))[c4];
        ((float4*)&As[r][0])[c4] = v;
    }
    __syncthreads();
    int ni = tid >> 4, oi = tid & 15;
    float acc = 0.f;
#pragma unroll 16
    for (int k4 = 0; k4 < 64; k4++) {
        float4 a = ((const float4*)&As[ni][0])[k4];
        float4 w = *(const float4*)&Wt[oi][k4 * 4];
        acc += a.x * w.x + a.y * w.y + a.z * w.z + a.w * w.w;
    }
    if (base + ni < n) C[(size_t)(base + ni) * 16 + oi] = acc;
}

// ------------------ eler for H=1,D=16: thread per node ----------------------
__global__ void eler1_kernel(const float* __restrict__ feat, const float* __restrict__ al,
                             const float* __restrict__ ar, float* __restrict__ el,
                             float* __restrict__ er) {
    int n = blockIdx.x * blockDim.x + threadIdx.x;
    if (n >= NN) return;
    const float4* fp = (const float4*)(feat + (size_t)n * 16);
    float sl = 0.f, sr = 0.f;
#pragma unroll
    for (int q = 0; q < 4; q++) {
        float4 f = fp[q];
        float4 a = ((const float4*)al)[q];
        float4 r = ((const float4*)ar)[q];
        sl += f.x * a.x + f.y * a.y + f.z * a.z + f.w * a.w;
        sr += f.x * r.x + f.y * r.y + f.z * r.z + f.w * r.w;
    }
    el[n] = sl; er[n] = sr;
}

// -------- fused softmax + aggregate, H=4, D=64 (2-pass, no max) -------------
template <int OUT_BF16>
__global__ void __launch_bounds__(256) gat_fused4(
    const int* __restrict__ rp, const int* __restrict__ cs,
    const float* __restrict__ el, const float* __restrict__ er,
    const float* __restrict__ feat, const float* __restrict__ bias,
    float* __restrict__ ebuf, float* __restrict__ outf,
    __nv_bfloat16* __restrict__ outhi, __nv_bfloat16* __restrict__ outlo)
{
    int warp = (blockIdx.x * blockDim.x + threadIdx.x) >> 5;
    int lane = threadIdx.x & 31;
    if (warp >= NN) return;
    int s0 = rp[warp], s1 = rp[warp + 1];

    float4 er4 = *(const float4*)&er[warp * 4];

    // pass AB: logits -> exp -> store + sum (no max subtraction; exact-math equal)
    float t0 = 0.f, t1 = 0.f, t2 = 0.f, t3 = 0.f;
    for (int i = s0 + lane; i < s1; i += 32) {
        int sn = cs[i];
        float4 lv = *(const float4*)&el[sn * 4];
        lv.x += er4.x; lv.y += er4.y; lv.z += er4.z; lv.w += er4.w;
        lv.x = lv.x > 0.f ? lv.x : 0.2f * lv.x;
        lv.y = lv.y > 0.f ? lv.y : 0.2f * lv.y;
        lv.z = lv.z > 0.f ? lv.z : 0.2f * lv.z;
        lv.w = lv.w > 0.f ? lv.w : 0.2f * lv.w;
        lv.x = __expf(lv.x); lv.y = __expf(lv.y);
        lv.z = __expf(lv.z); lv.w = __expf(lv.w);
        *(float4*)&ebuf[i * 4] = lv;
        t0 += lv.x; t1 += lv.y; t2 += lv.z; t3 += lv.w;
    }
#pragma unroll
    for (int o = 16; o; o >>= 1) {
        t0 += __shfl_xor_sync(0xffffffffu, t0, o);
        t1 += __shfl_xor_sync(0xffffffffu, t1, o);
        t2 += __shfl_xor_sync(0xffffffffu, t2, o);
        t3 += __shfl_xor_sync(0xffffffffu, t3, o);
    }

    int hl = lane >> 3;
    float sv = hl == 0 ? t0 : hl == 1 ? t1 : hl == 2 ? t2 : t3;
    float inv = 1.f / sv;

    // pass C: gather-aggregate into registers
    float a0 = 0.f, a1 = 0.f, a2 = 0.f, a3 = 0.f, a4 = 0.f, a5 = 0.f, a6 = 0.f, a7 = 0.f;
    for (int i = s0; i < s1; i++) {
        int sn = cs[i];
        float a = ebuf[i * 4 + hl] * inv;
        const float4* fp = (const float4*)(feat + (size_t)sn * 256 + lane * 8);
        float4 v0 = fp[0], v1 = fp[1];
        a0 += a * v0.x; a1 += a * v0.y; a2 += a * v0.z; a3 += a * v0.w;
        a4 += a * v1.x; a5 += a * v1.y; a6 += a * v1.z; a7 += a * v1.w;
    }
    const float4* bp = (const float4*)(bias + lane * 8);
    float4 b0 = bp[0], b1 = bp[1];
    float r[8] = { a0 + b0.x, a1 + b0.y, a2 + b0.z, a3 + b0.w,
                   a4 + b1.x, a5 + b1.y, a6 + b1.z, a7 + b1.w };
    if (OUT_BF16) {
        __nv_bfloat16 hi[8], lo[8];
#pragma unroll
        for (int q = 0; q < 8; q++) {
            hi[q] = __float2bfloat16(r[q]);
            lo[q] = __float2bfloat16(r[q] - __bfloat162float(hi[q]));
        }
        *(uint4*)(outhi + (size_t)warp * 256 + lane * 8) = *(const uint4*)hi;
        *(uint4*)(outlo + (size_t)warp * 256 + lane * 8) = *(const uint4*)lo;
    } else {
        float4* op = (float4*)(outf + (size_t)warp * 256 + lane * 8);
        op[0] = make_float4(r[0], r[1], r[2], r[3]);
        op[1] = make_float4(r[4], r[5], r[6], r[7]);
    }
}

// -------- fused softmax + aggregate, H=1, D=16 (2-pass, no max) -------------
__global__ void __launch_bounds__(256) gat_fused1(
    const int* __restrict__ rp, const int* __restrict__ cs,
    const float* __restrict__ el, const float* __restrict__ er,
    const float* __restrict__ feat, const float* __restrict__ bias,
    float* __restrict__ ebuf, float* __restrict__ out)
{
    int warp = (blockIdx.x * blockDim.x + threadIdx.x) >> 5;
    int lane = threadIdx.x & 31;
    if (warp >= NN) return;
    int s0 = rp[warp], s1 = rp[warp + 1];
    float erv = er[warp];

    float t = 0.f;
    for (int i = s0 + lane; i < s1; i += 32) {
        float x = el[cs[i]] + erv;
        x = x > 0.f ? x : 0.2f * x;
        float v = __expf(x);
        ebuf[i] = v;
        t += v;
    }
#pragma unroll
    for (int o = 16; o; o >>= 1) t += __shfl_xor_sync(0xffffffffu, t, o);
    float inv = 1.f / t;

    int half = lane >> 4, dk = lane & 15;
    float acc = 0.f;
    for (int i = s0 + half; i < s1; i += 2) {
        int sn = cs[i];
        float a = ebuf[i] * inv;
        acc += a * feat[(size_t)sn * 16 + dk];
    }
    acc += __shfl_xor_sync(0xffffffffu, acc, 16);
    if (lane < 16) out[(size_t)warp * 16 + lane] = acc + bias[lane];
}

// ---------------------------------------------------------------------------
extern "C" void kernel_launch(void* const* d_in, const int* in_sizes, int n_in,
                              void* d_out, int out_size) {
    const float* inputs = (const float*)d_in[0];
    const float* W0 = (const float*)d_in[1];
    const float* al0 = (const float*)d_in[2];
    const float* ar0 = (const float*)d_in[3];
    const float* b0 = (const float*)d_in[4];
    const float* W1 = (const float*)d_in[5];
    const float* al1 = (const float*)d_in[6];
    const float* ar1 = (const float*)d_in[7];
    const float* b1 = (const float*)d_in[8];
    const float* W2 = (const float*)d_in[9];
    const float* al2 = (const float*)d_in[10];
    const float* ar2 = (const float*)d_in[11];
    const float* b2 = (const float*)d_in[12];
    const int* src = (const int*)d_in[13];
    const int* dst = (const int*)d_in[14];

    float *feat, *h, *el, *er, *ebuf;
    int *cnt, *rpp, *cur, *csrc;
    __nv_bfloat16 *Ahi, *Alo, *Whi, *Wlo;
    cudaGetSymbolAddress((void**)&feat, g_feat);
    cudaGetSymbolAddress((void**)&h, g_h);
    cudaGetSymbolAddress((void**)&el, g_el);
    cudaGetSymbolAddress((void**)&er, g_er);
    cudaGetSymbolAddress((void**)&ebuf, g_e);
    cudaGetSymbolAddress((void**)&cnt, g_cnt);
    cudaGetSymbolAddress((void**)&rpp, g_rp);
    cudaGetSymbolAddress((void**)&cur, g_cur);
    cudaGetSymbolAddress((void**)&csrc, g_csrc);
    cudaGetSymbolAddress((void**)&Ahi, g_Ahi);
    cudaGetSymbolAddress((void**)&Alo, g_Alo);
    cudaGetSymbolAddress((void**)&Whi, g_Whi);
    cudaGetSymbolAddress((void**)&Wlo, g_Wlo);

    cudaFuncSetAttribute(hmma_gemm, cudaFuncAttributeMaxDynamicSharedMemorySize, HMMA_SMEM);

    int warpBlocks = (NN * 32 + 255) / 256;
    dim3 mmaGrid(2, (NN + 127) / 128);

    // ---------------- CSR build (graph is static across layers) ------------
    zero_cnt<<<(NN + 255) / 256, 256>>>(cnt);
    hist_kernel<<<(NE + 255) / 256, 256>>>(dst, cnt);
    scan_kernel<<<1, 1024>>>(cnt, rpp, cur);
    scatter_kernel<<<(NE + 255) / 256, 256>>>(src, dst, cur, csrc);

    // ---------------- Layer 0: 128 -> (4,64) ----------------
    convA_kernel<<<(NN * 128 / 4 + 255) / 256, 256>>>(inputs, Ahi, Alo, NN * 128 / 4);
    convW_kernel<<<(128 * 256 + 255) / 256, 256>>>(W0, Whi, Wlo, 128);
    zero_eler<<<(NN * 4 + 255) / 256, 256>>>(el, er);
    hmma_gemm<<<mmaGrid, 256, HMMA_SMEM>>>(Ahi, Alo, Whi, Wlo, feat, NN, 128,
                                           al0, ar0, el, er);
    gat_fused4<1><<<warpBlocks, 256>>>(rpp, csrc, el, er, feat, b0, ebuf,
                                       nullptr, Ahi, Alo);

    // ---------------- Layer 1: 256 -> (4,64) ----------------
    convW_kernel<<<(256 * 256 + 255) / 256, 256>>>(W1, Whi, Wlo, 256);
    zero_eler<<<(NN * 4 + 255) / 256, 256>>>(el, er);
    hmma_gemm<<<mmaGrid, 256, HMMA_SMEM>>>(Ahi, Alo, Whi, Wlo, feat, NN, 256,
                                           al1, ar1, el, er);
    gat_fused4<0><<<warpBlocks, 256>>>(rpp, csrc, el, er, feat, b1, ebuf,
                                       h, nullptr, nullptr);

    // ---------------- Layer 2: 256 -> (1,16), output logits ----------------
    float* out = (float*)d_out;
    gemm16<<<(NN + 15) / 16, 256>>>(h, W2, feat, NN);
    eler1_kernel<<<(NN + 255) / 256, 256>>>(feat, al2, ar2, el, er);
    gat_fused1<<<warpBlocks, 256>>>(rpp, csrc, el, er, feat, b2, ebuf, out);
}

// round 8
// speedup vs baseline: 2.3163x; 1.1624x over previous
#include <cuda_runtime.h>
#include <cuda_bf16.h>
#include <cstdint>

#define NN 50000
#define NE 800000
#define SCAN_BLOCKS 196
#define SCAN_CHUNK  ((NN + SCAN_BLOCKS - 1) / SCAN_BLOCKS)   // 256

// ------------------------- scratch (device globals) -------------------------
__device__ float    g_feat[NN * 256];
__device__ float    g_h[NN * 256];
__device__ float    g_el[NN * 4];
__device__ float    g_er[NN * 4];
__device__ float    g_e[NE * 4];        // per-edge exp values (CSR order)
__device__ int      g_cnt[NN];
__device__ int      g_rp[NN + 1];       // CSR row_ptr by dst
__device__ int      g_cur[NN];
__device__ int      g_csrc[NE];         // src per CSR slot
__device__ int      g_bsum[SCAN_BLOCKS];
__device__ __nv_bfloat16 g_Ahi[NN * 256];
__device__ __nv_bfloat16 g_Alo[NN * 256];
__device__ __nv_bfloat16 g_Whi[256 * 256];
__device__ __nv_bfloat16 g_Wlo[256 * 256];

__device__ __forceinline__ uint32_t smem_u32(const void* p) {
    uint32_t a;
    asm("{ .reg .u64 t; cvta.to.shared.u64 t, %1; cvt.u32.u64 %0, t; }" : "=r"(a) : "l"(p));
    return a;
}
__device__ __forceinline__ void cpa16(uint32_t s, const void* g) {
    asm volatile("cp.async.cg.shared.global [%0], [%1], 16;"
                 :: "r"(s), "l"(__cvta_generic_to_global(g)));
}

// ------------------------- CSR build ----------------------------------------
__global__ void init0_kernel(int* __restrict__ cnt, float* __restrict__ el,
                             float* __restrict__ er) {
    int i = blockIdx.x * blockDim.x + threadIdx.x;
    if (i < NN) cnt[i] = 0;
    if (i < NN * 4) { el[i] = 0.f; er[i] = 0.f; }
}
__global__ void hist_kernel(const int* __restrict__ dst, int* __restrict__ cnt) {
    int i = blockIdx.x * blockDim.x + threadIdx.x;
    if (i < NE) atomicAdd(&cnt[dst[i]], 1);
}
// phase 1: per-block sums of cnt
__global__ void scan_p1(const int* __restrict__ cnt, int* __restrict__ bsum) {
    __shared__ int red[256];
    int b = blockIdx.x, t = threadIdx.x;
    int beg = b * SCAN_CHUNK;
    int end = beg + SCAN_CHUNK; if (end > NN) end = NN;
    int s = 0;
    for (int i = beg + t; i < end; i += 256) s += cnt[i];
    red[t] = s;
    __syncthreads();
    for (int d = 128; d; d >>= 1) {
        if (t < d) red[t] += red[t + d];
        __syncthreads();
    }
    if (t == 0) bsum[b] = red[0];
}
// phase 2: exclusive scan of block sums (1 block)
__global__ void scan_p2(int* __restrict__ bsum) {
    __shared__ int v[SCAN_BLOCKS];
    int t = threadIdx.x;
    if (t < SCAN_BLOCKS) v[t] = bsum[t];
    __syncthreads();
    if (t == 0) {
        int acc = 0;
        for (int i = 0; i < SCAN_BLOCKS; i++) { int x = v[i]; v[i] = acc; acc += x; }
    }
    __syncthreads();
    if (t < SCAN_BLOCKS) bsum[t] = v[t];
}
// phase 3: within-block serial scan + write rp/cur
__global__ void scan_p3(const int* __restrict__ cnt, const int* __restrict__ bsum,
                        int* __restrict__ rp, int* __restrict__ cur) {
    int b = blockIdx.x, t = threadIdx.x;
    if (t != 0) return;                  // 1 thread per block does ~256 serial adds
    int beg = b * SCAN_CHUNK;
    int end = beg + SCAN_CHUNK; if (end > NN) end = NN;
    int off = bsum[b];
    for (int i = beg; i < end; i++) { rp[i] = off; cur[i] = off; off += cnt[i]; }
    if (b == SCAN_BLOCKS - 1) rp[NN] = NE;
}
__global__ void scatter_kernel(const int* __restrict__ src, const int* __restrict__ dst,
                               int* __restrict__ cur, int* __restrict__ csrc) {
    int i = blockIdx.x * blockDim.x + threadIdx.x;
    if (i >= NE) return;
    int p = atomicAdd(&cur[dst[i]], 1);
    csrc[p] = src[i];
}

// ------------------------- fp32 -> bf16 hi/lo converts ----------------------
__global__ void convA_kernel(const float* __restrict__ A, __nv_bfloat16* __restrict__ hi,
                             __nv_bfloat16* __restrict__ lo, int count4) {
    int i = blockIdx.x * blockDim.x + threadIdx.x;
    if (i >= count4) return;
    float4 v = ((const float4*)A)[i];
    __nv_bfloat16 h0 = __float2bfloat16(v.x), h1 = __float2bfloat16(v.y);
    __nv_bfloat16 h2 = __float2bfloat16(v.z), h3 = __float2bfloat16(v.w);
    __nv_bfloat16 l0 = __float2bfloat16(v.x - __bfloat162float(h0));
    __nv_bfloat16 l1 = __float2bfloat16(v.y - __bfloat162float(h1));
    __nv_bfloat16 l2 = __float2bfloat16(v.z - __bfloat162float(h2));
    __nv_bfloat16 l3 = __float2bfloat16(v.w - __bfloat162float(h3));
    __nv_bfloat162* ph = (__nv_bfloat162*)hi;
    __nv_bfloat162* pl = (__nv_bfloat162*)lo;
    ph[i * 2 + 0] = __nv_bfloat162(h0, h1);
    ph[i * 2 + 1] = __nv_bfloat162(h2, h3);
    pl[i * 2 + 0] = __nv_bfloat162(l0, l1);
    pl[i * 2 + 1] = __nv_bfloat162(l2, l3);
}

// also zeroes el/er (grid-stride) so no separate zero kernel is needed
__global__ void convW_kernel(const float* __restrict__ W, __nv_bfloat16* __restrict__ thi,
                             __nv_bfloat16* __restrict__ tlo, int kin,
                             float* __restrict__ el, float* __restrict__ er) {
    int i = blockIdx.x * blockDim.x + threadIdx.x;
    for (int j = i; j < NN * 4; j += gridDim.x * blockDim.x) { el[j] = 0.f; er[j] = 0.f; }
    if (i >= kin * 256) return;
    int k = i >> 8, o = i & 255;
    float v = W[i];
    __nv_bfloat16 h = __float2bfloat16(v);
    thi[o * kin + k] = h;
    tlo[o * kin + k] = __float2bfloat16(v - __bfloat162float(h));
}

// ------- HMMA GEMM, cp.async double-buffered, fused el/er epilogue ----------
#define HMMA_STAGE 65536
#define HMMA_SMEM  (2 * HMMA_STAGE)

__device__ __forceinline__ void mma16816(float* c, const uint32_t* a, const uint32_t* b) {
    asm volatile(
        "mma.sync.aligned.m16n8k16.row.col.f32.bf16.bf16.f32 "
        "{%0,%1,%2,%3}, {%4,%5,%6,%7}, {%8,%9}, {%0,%1,%2,%3};"
        : "+f"(c[0]), "+f"(c[1]), "+f"(c[2]), "+f"(c[3])
        : "r"(a[0]), "r"(a[1]), "r"(a[2]), "r"(a[3]), "r"(b[0]), "r"(b[1]));
}
__device__ __forceinline__ void ldsm4(uint32_t* r, uint32_t addr) {
    asm volatile("ldmatrix.sync.aligned.m8n8.x4.shared.b16 {%0,%1,%2,%3}, [%4];"
                 : "=r"(r[0]), "=r"(r[1]), "=r"(r[2]), "=r"(r[3]) : "r"(addr));
}

__global__ void __launch_bounds__(256, 1) hmma_gemm(
    const __nv_bfloat16* __restrict__ Ahi, const __nv_bfloat16* __restrict__ Alo,
    const __nv_bfloat16* __restrict__ Bhi, const __nv_bfloat16* __restrict__ Blo,
    float* __restrict__ C, int n, int kin,
    const float* __restrict__ alv, const float* __restrict__ arv,
    float* __restrict__ elo, float* __restrict__ ero)
{
    extern __shared__ char smem[];
    int tid = threadIdx.x, wid = tid >> 5, lane = tid & 31;
    int baseM = blockIdx.y * 128;
    int baseN = blockIdx.x * 128;
    int wm = wid >> 2, wn = wid & 3;

    float acc[4][4][4];
#pragma unroll
    for (int i = 0; i < 4; i++)
#pragma unroll
        for (int j = 0; j < 4; j++)
#pragma unroll
            for (int q = 0; q < 4; q++) acc[i][j][q] = 0.f;

    int arow = wm * 64 + (lane & 15);
    int ahalf16 = (lane >> 4) * 16;
    int brow = wn * 32 + ((lane >> 4) << 3) + (lane & 7);
    int bhalf16 = ((lane >> 3) & 1) * 16;

    uint32_t sb = smem_u32(smem);
    int nchunks = kin >> 6;

    auto load_chunk = [&](int kc, int stg) {
        uint32_t base = sb + stg * HMMA_STAGE;
#pragma unroll
        for (int it = 0; it < 4; it++) {
            int c = it * 256 + tid;
            int row = c >> 3, cj = c & 7;
            uint32_t off = row * 128 + ((cj * 16) ^ ((row & 7) << 4));
            int gr = baseM + row;
            if (gr < n) {
                size_t gi = (size_t)gr * kin + kc * 64 + cj * 8;
                cpa16(base + off, Ahi + gi);
                cpa16(base + 16384 + off, Alo + gi);
            } else {
                *(uint4*)(smem + stg * HMMA_STAGE + off) = make_uint4(0, 0, 0, 0);
                *(uint4*)(smem + stg * HMMA_STAGE + 16384 + off) = make_uint4(0, 0, 0, 0);
            }
            size_t wi = (size_t)(baseN + row) * kin + kc * 64 + cj * 8;
            cpa16(base + 32768 + off, Bhi + wi);
            cpa16(base + 49152 + off, Blo + wi);
        }
        asm volatile("cp.async.commit_group;" ::: "memory");
    };

    load_chunk(0, 0);
    for (int kc = 0; kc < nchunks; kc++) {
        if (kc + 1 < nchunks) {
            load_chunk(kc + 1, (kc + 1) & 1);
            asm volatile("cp.async.wait_group 1;" ::: "memory");
        } else {
            asm volatile("cp.async.wait_group 0;" ::: "memory");
        }
        __syncthreads();

        uint32_t sA  = sb + (kc & 1) * HMMA_STAGE;
        uint32_t sAl = sA + 16384;
        uint32_t sW  = sA + 32768;
        uint32_t sWl = sA + 49152;
#pragma unroll
        for (int s = 0; s < 4; s++) {
            uint32_t ah[4][4], al_[4][4], bh[2][4], bl[2][4];
#pragma unroll
            for (int mi = 0; mi < 4; mi++) {
                int r = arow + mi * 16;
                uint32_t off = r * 128 + ((s * 32 + ahalf16) ^ ((r & 7) << 4));
                ldsm4(ah[mi], sA + off);
                ldsm4(al_[mi], sAl + off);
            }
#pragma unroll
            for (int p = 0; p < 2; p++) {
                int r = brow + p * 16;
                uint32_t off = r * 128 + ((s * 32 + bhalf16) ^ ((r & 7) << 4));
                ldsm4(bh[p], sW + off);
                ldsm4(bl[p], sWl + off);
            }
#pragma unroll
            for (int mi = 0; mi < 4; mi++)
#pragma unroll
                for (int p = 0; p < 2; p++)
#pragma unroll
                    for (int q = 0; q < 2; q++) {
                        int t = p * 2 + q;
                        mma16816(acc[mi][t], ah[mi], &bh[p][q * 2]);
                        mma16816(acc[mi][t], ah[mi], &bl[p][q * 2]);
                        mma16816(acc[mi][t], al_[mi], &bh[p][q * 2]);
                    }
        }
        __syncthreads();
    }

    int g = lane >> 2, t4 = lane & 3;

    // ---- write C ----
#pragma unroll
    for (int mi = 0; mi < 4; mi++) {
        int r0 = baseM + wm * 64 + mi * 16 + g;
        int r1 = r0 + 8;
#pragma unroll
        for (int t = 0; t < 4; t++) {
            int col = baseN + wn * 32 + t * 8 + t4 * 2;
            if (r0 < n) *(float2*)(C + (size_t)r0 * 256 + col) = make_float2(acc[mi][t][0], acc[mi][t][1]);
            if (r1 < n) *(float2*)(C + (size_t)r1 * 256 + col) = make_float2(acc[mi][t][2], acc[mi][t][3]);
        }
    }

    // ---- fused el/er epilogue ----
    int hh = (baseN + wn * 32) >> 6;
    float av[4][2], rv[4][2];
#pragma unroll
    for (int t = 0; t < 4; t++) {
        int col = baseN + wn * 32 + t * 8 + t4 * 2;
        av[t][0] = alv[col]; av[t][1] = alv[col + 1];
        rv[t][0] = arv[col]; rv[t][1] = arv[col + 1];
    }
#pragma unroll
    for (int mi = 0; mi < 4; mi++) {
        float e0 = 0.f, e1 = 0.f, f0 = 0.f, f1 = 0.f;
#pragma unroll
        for (int t = 0; t < 4; t++) {
            e0 += acc[mi][t][0] * av[t][0] + acc[mi][t][1] * av[t][1];
            e1 += acc[mi][t][2] * av[t][0] + acc[mi][t][3] * av[t][1];
            f0 += acc[mi][t][0] * rv[t][0] + acc[mi][t][1] * rv[t][1];
            f1 += acc[mi][t][2] * rv[t][0] + acc[mi][t][3] * rv[t][1];
        }
#pragma unroll
        for (int o = 1; o <= 2; o <<= 1) {
            e0 += __shfl_xor_sync(0xffffffffu, e0, o);
            e1 += __shfl_xor_sync(0xffffffffu, e1, o);
            f0 += __shfl_xor_sync(0xffffffffu, f0, o);
            f1 += __shfl_xor_sync(0xffffffffu, f1, o);
        }
        if (t4 == 0) {
            int r0 = baseM + wm * 64 + mi * 16 + g;
            int r1 = r0 + 8;
            if (r0 < n) { atomicAdd(&elo[r0 * 4 + hh], e0); atomicAdd(&ero[r0 * 4 + hh], f0); }
            if (r1 < n) { atomicAdd(&elo[r1 * 4 + hh], e1); atomicAdd(&ero[r1 * 4 + hh], f1); }
        }
    }
}

// --------- small GEMM for layer 2 (kin=256, kout=16) + fused el/er ----------
__global__ void gemm16(const float* __restrict__ A, const float* __restrict__ W,
                       float* __restrict__ C, int n,
                       const float* __restrict__ alv, const float* __restrict__ arv,
                       float* __restrict__ elo, float* __restrict__ ero) {
    __shared__ float As[16][256];
    __shared__ float Wt[16][260];
    int tid = threadIdx.x;
    int base = blockIdx.x * 16;
    for (int i = tid; i < 4096; i += 256) {
        int k = i >> 4, oi = i & 15;
        Wt[oi][k] = W[i];
    }
    for (int i = tid; i < 1024; i += 256) {
        int r = i >> 6, c4 = i & 63;
        float4 v = make_float4(0.f, 0.f, 0.f, 0.f);
        if (base + r < n) v = ((const float4*)(A + (size_t)(base + r) * 256))[c4];
        ((float4*)&As[r][0])[c4] = v;
    }
    __syncthreads();
    int ni = tid >> 4, oi = tid & 15;
    float acc = 0.f;
#pragma unroll 16
    for (int k4 = 0; k4 < 64; k4++) {
        float4 a = ((const float4*)&As[ni][0])[k4];
        float4 w = *(const float4*)&Wt[oi][k4 * 4];
        acc += a.x * w.x + a.y * w.y + a.z * w.z + a.w * w.w;
    }
    if (base + ni < n) C[(size_t)(base + ni) * 16 + oi] = acc;

    // fused el/er: reduce acc*al / acc*ar over the 16 oi lanes of this row.
    // lanes [ni*16 .. ni*16+15] sit in the same warp half; use shfl tree.
    float e = acc * alv[oi], f = acc * arv[oi];
#pragma unroll
    for (int o = 8; o; o >>= 1) {
        e += __shfl_xor_sync(0xffffffffu, e, o);
        f += __shfl_xor_sync(0xffffffffu, f, o);
    }
    if (oi == 0 && base + ni < n) { elo[base + ni] = e; ero[base + ni] = f; }
}

// -------- fused softmax + aggregate, H=4, D=64 (2-pass, no max) -------------
template <int OUT_BF16>
__global__ void __launch_bounds__(256) gat_fused4(
    const int* __restrict__ rp, const int* __restrict__ cs,
    const float* __restrict__ el, const float* __restrict__ er,
    const float* __restrict__ feat, const float* __restrict__ bias,
    float* __restrict__ ebuf, float* __restrict__ outf,
    __nv_bfloat16* __restrict__ outhi, __nv_bfloat16* __restrict__ outlo)
{
    int warp = (blockIdx.x * blockDim.x + threadIdx.x) >> 5;
    int lane = threadIdx.x & 31;
    if (warp >= NN) return;
    int s0 = rp[warp], s1 = rp[warp + 1];

    float4 er4 = *(const float4*)&er[warp * 4];

    // pass AB: logits -> exp -> store + sum
    float t0 = 0.f, t1 = 0.f, t2 = 0.f, t3 = 0.f;
    for (int i = s0 + lane; i < s1; i += 32) {
        int sn = cs[i];
        float4 lv = *(const float4*)&el[sn * 4];
        lv.x += er4.x; lv.y += er4.y; lv.z += er4.z; lv.w += er4.w;
        lv.x = lv.x > 0.f ? lv.x : 0.2f * lv.x;
        lv.y = lv.y > 0.f ? lv.y : 0.2f * lv.y;
        lv.z = lv.z > 0.f ? lv.z : 0.2f * lv.z;
        lv.w = lv.w > 0.f ? lv.w : 0.2f * lv.w;
        lv.x = __expf(lv.x); lv.y = __expf(lv.y);
        lv.z = __expf(lv.z); lv.w = __expf(lv.w);
        *(float4*)&ebuf[i * 4] = lv;
        t0 += lv.x; t1 += lv.y; t2 += lv.z; t3 += lv.w;
    }
#pragma unroll
    for (int o = 16; o; o >>= 1) {
        t0 += __shfl_xor_sync(0xffffffffu, t0, o);
        t1 += __shfl_xor_sync(0xffffffffu, t1, o);
        t2 += __shfl_xor_sync(0xffffffffu, t2, o);
        t3 += __shfl_xor_sync(0xffffffffu, t3, o);
    }

    int hl = lane >> 3;
    float sv = hl == 0 ? t0 : hl == 1 ? t1 : hl == 2 ? t2 : t3;
    float inv = 1.f / sv;

    // pass C: gather-aggregate, unrolled x2 with prefetched index+alpha
    float a0 = 0.f, a1 = 0.f, a2 = 0.f, a3 = 0.f, a4 = 0.f, a5 = 0.f, a6 = 0.f, a7 = 0.f;
    int i = s0;
    for (; i + 2 <= s1; i += 2) {
        int sn0 = cs[i], sn1 = cs[i + 1];
        float aa0 = ebuf[i * 4 + hl] * inv;
        float aa1 = ebuf[(i + 1) * 4 + hl] * inv;
        const float4* fp0 = (const float4*)(feat + (size_t)sn0 * 256 + lane * 8);
        const float4* fp1 = (const float4*)(feat + (size_t)sn1 * 256 + lane * 8);
        float4 u0 = fp0[0], u1 = fp0[1];
        float4 w0 = fp1[0], w1 = fp1[1];
        a0 += aa0 * u0.x + aa1 * w0.x; a1 += aa0 * u0.y + aa1 * w0.y;
        a2 += aa0 * u0.z + aa1 * w0.z; a3 += aa0 * u0.w + aa1 * w0.w;
        a4 += aa0 * u1.x + aa1 * w1.x; a5 += aa0 * u1.y + aa1 * w1.y;
        a6 += aa0 * u1.z + aa1 * w1.z; a7 += aa0 * u1.w + aa1 * w1.w;
    }
    if (i < s1) {
        int sn = cs[i];
        float a = ebuf[i * 4 + hl] * inv;
        const float4* fp = (const float4*)(feat + (size_t)sn * 256 + lane * 8);
        float4 v0 = fp[0], v1 = fp[1];
        a0 += a * v0.x; a1 += a * v0.y; a2 += a * v0.z; a3 += a * v0.w;
        a4 += a * v1.x; a5 += a * v1.y; a6 += a * v1.z; a7 += a * v1.w;
    }
    const float4* bp = (const float4*)(bias + lane * 8);
    float4 b0 = bp[0], b1 = bp[1];
    float r[8] = { a0 + b0.x, a1 + b0.y, a2 + b0.z, a3 + b0.w,
                   a4 + b1.x, a5 + b1.y, a6 + b1.z, a7 + b1.w };
    if (OUT_BF16) {
        __nv_bfloat16 hi[8], lo[8];
#pragma unroll
        for (int q = 0; q < 8; q++) {
            hi[q] = __float2bfloat16(r[q]);
            lo[q] = __float2bfloat16(r[q] - __bfloat162float(hi[q]));
        }
        *(uint4*)(outhi + (size_t)warp * 256 + lane * 8) = *(const uint4*)hi;
        *(uint4*)(outlo + (size_t)warp * 256 + lane * 8) = *(const uint4*)lo;
    } else {
        float4* op = (float4*)(outf + (size_t)warp * 256 + lane * 8);
        op[0] = make_float4(r[0], r[1], r[2], r[3]);
        op[1] = make_float4(r[4], r[5], r[6], r[7]);
    }
}

// -------- fused softmax + aggregate, H=1, D=16 (2-pass, no max) -------------
__global__ void __launch_bounds__(256) gat_fused1(
    const int* __restrict__ rp, const int* __restrict__ cs,
    const float* __restrict__ el, const float* __restrict__ er,
    const float* __restrict__ feat, const float* __restrict__ bias,
    float* __restrict__ ebuf, float* __restrict__ out)
{
    int warp = (blockIdx.x * blockDim.x + threadIdx.x) >> 5;
    int lane = threadIdx.x & 31;
    if (warp >= NN) return;
    int s0 = rp[warp], s1 = rp[warp + 1];
    float erv = er[warp];

    float t = 0.f;
    for (int i = s0 + lane; i < s1; i += 32) {
        float x = el[cs[i]] + erv;
        x = x > 0.f ? x : 0.2f * x;
        float v = __expf(x);
        ebuf[i] = v;
        t += v;
    }
#pragma unroll
    for (int o = 16; o; o >>= 1) t += __shfl_xor_sync(0xffffffffu, t, o);
    float inv = 1.f / t;

    int half = lane >> 4, dk = lane & 15;
    float acc = 0.f;
    for (int i = s0 + half; i < s1; i += 2) {
        int sn = cs[i];
        float a = ebuf[i] * inv;
        acc += a * feat[(size_t)sn * 16 + dk];
    }
    acc += __shfl_xor_sync(0xffffffffu, acc, 16);
    if (lane < 16) out[(size_t)warp * 16 + lane] = acc + bias[lane];
}

// ---------------------------------------------------------------------------
extern "C" void kernel_launch(void* const* d_in, const int* in_sizes, int n_in,
                              void* d_out, int out_size) {
    const float* inputs = (const float*)d_in[0];
    const float* W0 = (const float*)d_in[1];
    const float* al0 = (const float*)d_in[2];
    const float* ar0 = (const float*)d_in[3];
    const float* b0 = (const float*)d_in[4];
    const float* W1 = (const float*)d_in[5];
    const float* al1 = (const float*)d_in[6];
    const float* ar1 = (const float*)d_in[7];
    const float* b1 = (const float*)d_in[8];
    const float* W2 = (const float*)d_in[9];
    const float* al2 = (const float*)d_in[10];
    const float* ar2 = (const float*)d_in[11];
    const float* b2 = (const float*)d_in[12];
    const int* src = (const int*)d_in[13];
    const int* dst = (const int*)d_in[14];

    float *feat, *h, *el, *er, *ebuf;
    int *cnt, *rpp, *cur, *csrc, *bsum;
    __nv_bfloat16 *Ahi, *Alo, *Whi, *Wlo;
    cudaGetSymbolAddress((void**)&feat, g_feat);
    cudaGetSymbolAddress((void**)&h, g_h);
    cudaGetSymbolAddress((void**)&el, g_el);
    cudaGetSymbolAddress((void**)&er, g_er);
    cudaGetSymbolAddress((void**)&ebuf, g_e);
    cudaGetSymbolAddress((void**)&cnt, g_cnt);
    cudaGetSymbolAddress((void**)&rpp, g_rp);
    cudaGetSymbolAddress((void**)&cur, g_cur);
    cudaGetSymbolAddress((void**)&csrc, g_csrc);
    cudaGetSymbolAddress((void**)&bsum, g_bsum);
    cudaGetSymbolAddress((void**)&Ahi, g_Ahi);
    cudaGetSymbolAddress((void**)&Alo, g_Alo);
    cudaGetSymbolAddress((void**)&Whi, g_Whi);
    cudaGetSymbolAddress((void**)&Wlo, g_Wlo);

    cudaFuncSetAttribute(hmma_gemm, cudaFuncAttributeMaxDynamicSharedMemorySize, HMMA_SMEM);

    int warpBlocks = (NN * 32 + 255) / 256;
    dim3 mmaGrid(2, (NN + 127) / 128);

    // ---------------- CSR build + zero el/er -------------------------------
    init0_kernel<<<(NN * 4 + 255) / 256, 256>>>(cnt, el, er);
    hist_kernel<<<(NE + 255) / 256, 256>>>(dst, cnt);
    scan_p1<<<SCAN_BLOCKS, 256>>>(cnt, bsum);
    scan_p2<<<1, 256>>>(bsum);
    scan_p3<<<SCAN_BLOCKS, 32>>>(cnt, bsum, rpp, cur);
    scatter_kernel<<<(NE + 255) / 256, 256>>>(src, dst, cur, csrc);

    // ---------------- Layer 0: 128 -> (4,64) ----------------
    convA_kernel<<<(NN * 128 / 4 + 255) / 256, 256>>>(inputs, Ahi, Alo, NN * 128 / 4);
    convW_kernel<<<(128 * 256 + 255) / 256, 256>>>(W0, Whi, Wlo, 128, el, er);  // el/er already zero; harmless re-zero
    hmma_gemm<<<mmaGrid, 256, HMMA_SMEM>>>(Ahi, Alo, Whi, Wlo, feat, NN, 128,
                                           al0, ar0, el, er);
    gat_fused4<1><<<warpBlocks, 256>>>(rpp, csrc, el, er, feat, b0, ebuf,
                                       nullptr, Ahi, Alo);

    // ---------------- Layer 1: 256 -> (4,64) ----------------
    convW_kernel<<<(256 * 256 + 255) / 256, 256>>>(W1, Whi, Wlo, 256, el, er);  // zeroes el/er for layer 1
    hmma_gemm<<<mmaGrid, 256, HMMA_SMEM>>>(Ahi, Alo, Whi, Wlo, feat, NN, 256,
                                           al1, ar1, el, er);
    gat_fused4<0><<<warpBlocks, 256>>>(rpp, csrc, el, er, feat, b1, ebuf,
                                       h, nullptr, nullptr);

    // ---------------- Layer 2: 256 -> (1,16), output logits ----------------
    float* out = (float*)d_out;
    gemm16<<<(NN + 15) / 16, 256>>>(h, W2, feat, NN, al2, ar2, el, er);
    gat_fused1<<<warpBlocks, 256>>>(rpp, csrc, el, er, feat, b2, ebuf, out);
}

// round 9
// speedup vs baseline: 2.4092x; 1.0401x over previous
#include <cuda_runtime.h>
#include <cuda_bf16.h>
#include <cstdint>

#define NN 50000
#define NE 800000
#define SCAN_BLOCKS 196
#define SCAN_CHUNK  ((NN + SCAN_BLOCKS - 1) / SCAN_BLOCKS)   // 256

// ------------------------- scratch (device globals) -------------------------
__device__ float    g_feat[NN * 256];
__device__ float    g_h[NN * 256];
__device__ float    g_el[NN * 4];
__device__ float    g_er[NN * 4];
__device__ float    g_el2[NN * 4];
__device__ float    g_er2[NN * 4];
__device__ float    g_e[NE * 4];        // per-edge exp values (CSR order)
__device__ int      g_cnt[NN];
__device__ int      g_rp[NN + 1];       // CSR row_ptr by dst
__device__ int      g_cur[NN];
__device__ int      g_csrc[NE];         // src per CSR slot
__device__ int      g_bsum[SCAN_BLOCKS];
__device__ __nv_bfloat16 g_Ahi[NN * 256];
__device__ __nv_bfloat16 g_Alo[NN * 256];
__device__ __nv_bfloat16 g_Whi[256 * 256];
__device__ __nv_bfloat16 g_Wlo[256 * 256];
__device__ __nv_bfloat16 g_Whi2[256 * 256];
__device__ __nv_bfloat16 g_Wlo2[256 * 256];

__device__ __forceinline__ uint32_t smem_u32(const void* p) {
    uint32_t a;
    asm("{ .reg .u64 t; cvta.to.shared.u64 t, %1; cvt.u32.u64 %0, t; }" : "=r"(a) : "l"(p));
    return a;
}
__device__ __forceinline__ void cpa16(uint32_t s, const void* g) {
    asm volatile("cp.async.cg.shared.global [%0], [%1], 16;"
                 :: "r"(s), "l"(__cvta_generic_to_global(g)));
}

// ------------------------- CSR build ----------------------------------------
__global__ void init_cnt(int* __restrict__ cnt) {
    int i = blockIdx.x * blockDim.x + threadIdx.x;
    if (i < NN) cnt[i] = 0;
}
__global__ void hist_kernel(const int* __restrict__ dst, int* __restrict__ cnt) {
    int i = blockIdx.x * blockDim.x + threadIdx.x;
    if (i < NE) atomicAdd(&cnt[dst[i]], 1);
}
__global__ void scan_p1(const int* __restrict__ cnt, int* __restrict__ bsum) {
    __shared__ int red[256];
    int b = blockIdx.x, t = threadIdx.x;
    int beg = b * SCAN_CHUNK;
    int end = beg + SCAN_CHUNK; if (end > NN) end = NN;
    int s = 0;
    for (int i = beg + t; i < end; i += 256) s += cnt[i];
    red[t] = s;
    __syncthreads();
    for (int d = 128; d; d >>= 1) {
        if (t < d) red[t] += red[t + d];
        __syncthreads();
    }
    if (t == 0) bsum[b] = red[0];
}
// parallel exclusive scan of 196 block sums (Hillis-Steele in smem)
__global__ void scan_p2(int* __restrict__ bsum) {
    __shared__ int v[256];
    int t = threadIdx.x;
    v[t] = (t < SCAN_BLOCKS) ? bsum[t] : 0;
    __syncthreads();
#pragma unroll
    for (int d = 1; d < 256; d <<= 1) {
        int x = (t >= d) ? v[t - d] : 0;
        __syncthreads();
        v[t] += x;
        __syncthreads();
    }
    if (t < SCAN_BLOCKS) bsum[t] = (t > 0) ? v[t - 1] : 0;   // exclusive
}
__global__ void scan_p3(const int* __restrict__ cnt, const int* __restrict__ bsum,
                        int* __restrict__ rp, int* __restrict__ cur) {
    int b = blockIdx.x, t = threadIdx.x;
    if (t != 0) return;
    int beg = b * SCAN_CHUNK;
    int end = beg + SCAN_CHUNK; if (end > NN) end = NN;
    int off = bsum[b];
    for (int i = beg; i < end; i++) { rp[i] = off; cur[i] = off; off += cnt[i]; }
    if (b == SCAN_BLOCKS - 1) rp[NN] = NE;
}
__global__ void scatter_kernel(const int* __restrict__ src, const int* __restrict__ dst,
                               int* __restrict__ cur, int* __restrict__ csrc) {
    int i = blockIdx.x * blockDim.x + threadIdx.x;
    if (i >= NE) return;
    int p = atomicAdd(&cur[dst[i]], 1);
    csrc[p] = src[i];
}

// ------------------------- fp32 -> bf16 hi/lo converts ----------------------
__global__ void convA_kernel(const float* __restrict__ A, __nv_bfloat16* __restrict__ hi,
                             __nv_bfloat16* __restrict__ lo, int count4) {
    int i = blockIdx.x * blockDim.x + threadIdx.x;
    if (i >= count4) return;
    float4 v = ((const float4*)A)[i];
    __nv_bfloat16 h0 = __float2bfloat16(v.x), h1 = __float2bfloat16(v.y);
    __nv_bfloat16 h2 = __float2bfloat16(v.z), h3 = __float2bfloat16(v.w);
    __nv_bfloat16 l0 = __float2bfloat16(v.x - __bfloat162float(h0));
    __nv_bfloat16 l1 = __float2bfloat16(v.y - __bfloat162float(h1));
    __nv_bfloat16 l2 = __float2bfloat16(v.z - __bfloat162float(h2));
    __nv_bfloat16 l3 = __float2bfloat16(v.w - __bfloat162float(h3));
    __nv_bfloat162* ph = (__nv_bfloat162*)hi;
    __nv_bfloat162* pl = (__nv_bfloat162*)lo;
    ph[i * 2 + 0] = __nv_bfloat162(h0, h1);
    ph[i * 2 + 1] = __nv_bfloat162(h2, h3);
    pl[i * 2 + 0] = __nv_bfloat162(l0, l1);
    pl[i * 2 + 1] = __nv_bfloat162(l2, l3);
}

// converts W and zeroes the passed el/er pair
__global__ void convW_kernel(const float* __restrict__ W, __nv_bfloat16* __restrict__ thi,
                             __nv_bfloat16* __restrict__ tlo, int kin,
                             float* __restrict__ el, float* __restrict__ er) {
    int i = blockIdx.x * blockDim.x + threadIdx.x;
    for (int j = i; j < NN * 4; j += gridDim.x * blockDim.x) { el[j] = 0.f; er[j] = 0.f; }
    if (i >= kin * 256) return;
    int k = i >> 8, o = i & 255;
    float v = W[i];
    __nv_bfloat16 h = __float2bfloat16(v);
    thi[o * kin + k] = h;
    tlo[o * kin + k] = __float2bfloat16(v - __bfloat162float(h));
}

// ------- HMMA GEMM, cp.async double-buffered, fused el/er epilogue ----------
#define HMMA_STAGE 65536
#define HMMA_SMEM  (2 * HMMA_STAGE)

__device__ __forceinline__ void mma16816(float* c, const uint32_t* a, const uint32_t* b) {
    asm volatile(
        "mma.sync.aligned.m16n8k16.row.col.f32.bf16.bf16.f32 "
        "{%0,%1,%2,%3}, {%4,%5,%6,%7}, {%8,%9}, {%0,%1,%2,%3};"
        : "+f"(c[0]), "+f"(c[1]), "+f"(c[2]), "+f"(c[3])
        : "r"(a[0]), "r"(a[1]), "r"(a[2]), "r"(a[3]), "r"(b[0]), "r"(b[1]));
}
__device__ __forceinline__ void ldsm4(uint32_t* r, uint32_t addr) {
    asm volatile("ldmatrix.sync.aligned.m8n8.x4.shared.b16 {%0,%1,%2,%3}, [%4];"
                 : "=r"(r[0]), "=r"(r[1]), "=r"(r[2]), "=r"(r[3]) : "r"(addr));
}

__global__ void __launch_bounds__(256, 1) hmma_gemm(
    const __nv_bfloat16* __restrict__ Ahi, const __nv_bfloat16* __restrict__ Alo,
    const __nv_bfloat16* __restrict__ Bhi, const __nv_bfloat16* __restrict__ Blo,
    float* __restrict__ C, int n, int kin,
    const float* __restrict__ alv, const float* __restrict__ arv,
    float* __restrict__ elo, float* __restrict__ ero)
{
    extern __shared__ char smem[];
    int tid = threadIdx.x, wid = tid >> 5, lane = tid & 31;
    int baseM = blockIdx.y * 128;
    int baseN = blockIdx.x * 128;
    int wm = wid >> 2, wn = wid & 3;

    float acc[4][4][4];
#pragma unroll
    for (int i = 0; i < 4; i++)
#pragma unroll
        for (int j = 0; j < 4; j++)
#pragma unroll
            for (int q = 0; q < 4; q++) acc[i][j][q] = 0.f;

    int arow = wm * 64 + (lane & 15);
    int ahalf16 = (lane >> 4) * 16;
    int brow = wn * 32 + ((lane >> 4) << 3) + (lane & 7);
    int bhalf16 = ((lane >> 3) & 1) * 16;

    uint32_t sb = smem_u32(smem);
    int nchunks = kin >> 6;

    auto load_chunk = [&](int kc, int stg) {
        uint32_t base = sb + stg * HMMA_STAGE;
#pragma unroll
        for (int it = 0; it < 4; it++) {
            int c = it * 256 + tid;
            int row = c >> 3, cj = c & 7;
            uint32_t off = row * 128 + ((cj * 16) ^ ((row & 7) << 4));
            int gr = baseM + row;
            if (gr < n) {
                size_t gi = (size_t)gr * kin + kc * 64 + cj * 8;
                cpa16(base + off, Ahi + gi);
                cpa16(base + 16384 + off, Alo + gi);
            } else {
                *(uint4*)(smem + stg * HMMA_STAGE + off) = make_uint4(0, 0, 0, 0);
                *(uint4*)(smem + stg * HMMA_STAGE + 16384 + off) = make_uint4(0, 0, 0, 0);
            }
            size_t wi = (size_t)(baseN + row) * kin + kc * 64 + cj * 8;
            cpa16(base + 32768 + off, Bhi + wi);
            cpa16(base + 49152 + off, Blo + wi);
        }
        asm volatile("cp.async.commit_group;" ::: "memory");
    };

    load_chunk(0, 0);
    for (int kc = 0; kc < nchunks; kc++) {
        if (kc + 1 < nchunks) {
            load_chunk(kc + 1, (kc + 1) & 1);
            asm volatile("cp.async.wait_group 1;" ::: "memory");
        } else {
            asm volatile("cp.async.wait_group 0;" ::: "memory");
        }
        __syncthreads();

        uint32_t sA  = sb + (kc & 1) * HMMA_STAGE;
        uint32_t sAl = sA + 16384;
        uint32_t sW  = sA + 32768;
        uint32_t sWl = sA + 49152;
#pragma unroll
        for (int s = 0; s < 4; s++) {
            uint32_t ah[4][4], al_[4][4], bh[2][4], bl[2][4];
#pragma unroll
            for (int mi = 0; mi < 4; mi++) {
                int r = arow + mi * 16;
                uint32_t off = r * 128 + ((s * 32 + ahalf16) ^ ((r & 7) << 4));
                ldsm4(ah[mi], sA + off);
                ldsm4(al_[mi], sAl + off);
            }
#pragma unroll
            for (int p = 0; p < 2; p++) {
                int r = brow + p * 16;
                uint32_t off = r * 128 + ((s * 32 + bhalf16) ^ ((r & 7) << 4));
                ldsm4(bh[p], sW + off);
                ldsm4(bl[p], sWl + off);
            }
#pragma unroll
            for (int mi = 0; mi < 4; mi++)
#pragma unroll
                for (int p = 0; p < 2; p++)
#pragma unroll
                    for (int q = 0; q < 2; q++) {
                        int t = p * 2 + q;
                        mma16816(acc[mi][t], ah[mi], &bh[p][q * 2]);
                        mma16816(acc[mi][t], ah[mi], &bl[p][q * 2]);
                        mma16816(acc[mi][t], al_[mi], &bh[p][q * 2]);
                    }
        }
        __syncthreads();
    }

    int g = lane >> 2, t4 = lane & 3;

#pragma unroll
    for (int mi = 0; mi < 4; mi++) {
        int r0 = baseM + wm * 64 + mi * 16 + g;
        int r1 = r0 + 8;
#pragma unroll
        for (int t = 0; t < 4; t++) {
            int col = baseN + wn * 32 + t * 8 + t4 * 2;
            if (r0 < n) *(float2*)(C + (size_t)r0 * 256 + col) = make_float2(acc[mi][t][0], acc[mi][t][1]);
            if (r1 < n) *(float2*)(C + (size_t)r1 * 256 + col) = make_float2(acc[mi][t][2], acc[mi][t][3]);
        }
    }

    int hh = (baseN + wn * 32) >> 6;
    float av[4][2], rv[4][2];
#pragma unroll
    for (int t = 0; t < 4; t++) {
        int col = baseN + wn * 32 + t * 8 + t4 * 2;
        av[t][0] = alv[col]; av[t][1] = alv[col + 1];
        rv[t][0] = arv[col]; rv[t][1] = arv[col + 1];
    }
#pragma unroll
    for (int mi = 0; mi < 4; mi++) {
        float e0 = 0.f, e1 = 0.f, f0 = 0.f, f1 = 0.f;
#pragma unroll
        for (int t = 0; t < 4; t++) {
            e0 += acc[mi][t][0] * av[t][0] + acc[mi][t][1] * av[t][1];
            e1 += acc[mi][t][2] * av[t][0] + acc[mi][t][3] * av[t][1];
            f0 += acc[mi][t][0] * rv[t][0] + acc[mi][t][1] * rv[t][1];
            f1 += acc[mi][t][2] * rv[t][0] + acc[mi][t][3] * rv[t][1];
        }
#pragma unroll
        for (int o = 1; o <= 2; o <<= 1) {
            e0 += __shfl_xor_sync(0xffffffffu, e0, o);
            e1 += __shfl_xor_sync(0xffffffffu, e1, o);
            f0 += __shfl_xor_sync(0xffffffffu, f0, o);
            f1 += __shfl_xor_sync(0xffffffffu, f1, o);
        }
        if (t4 == 0) {
            int r0 = baseM + wm * 64 + mi * 16 + g;
            int r1 = r0 + 8;
            if (r0 < n) { atomicAdd(&elo[r0 * 4 + hh], e0); atomicAdd(&ero[r0 * 4 + hh], f0); }
            if (r1 < n) { atomicAdd(&elo[r1 * 4 + hh], e1); atomicAdd(&ero[r1 * 4 + hh], f1); }
        }
    }
}

// --------- small GEMM for layer 2 (kin=256, kout=16) + fused el/er ----------
__global__ void gemm16(const float* __restrict__ A, const float* __restrict__ W,
                       float* __restrict__ C, int n,
                       const float* __restrict__ alv, const float* __restrict__ arv,
                       float* __restrict__ elo, float* __restrict__ ero) {
    __shared__ float As[16][256];
    __shared__ float Wt[16][260];
    int tid = threadIdx.x;
    int base = blockIdx.x * 16;
    for (int i = tid; i < 4096; i += 256) {
        int k = i >> 4, oi = i & 15;
        Wt[oi][k] = W[i];
    }
    for (int i = tid; i < 1024; i += 256) {
        int r = i >> 6, c4 = i & 63;
        float4 v = make_float4(0.f, 0.f, 0.f, 0.f);
        if (base + r < n) v = ((const float4*)(A + (size_t)(base + r) * 256))[c4];
        ((float4*)&As[r][0])[c4] = v;
    }
    __syncthreads();
    int ni = tid >> 4, oi = tid & 15;
    float acc = 0.f;
#pragma unroll 16
    for (int k4 = 0; k4 < 64; k4++) {
        float4 a = ((const float4*)&As[ni][0])[k4];
        float4 w = *(const float4*)&Wt[oi][k4 * 4];
        acc += a.x * w.x + a.y * w.y + a.z * w.z + a.w * w.w;
    }
    if (base + ni < n) C[(size_t)(base + ni) * 16 + oi] = acc;

    float e = acc * alv[oi], f = acc * arv[oi];
#pragma unroll
    for (int o = 8; o; o >>= 1) {
        e += __shfl_xor_sync(0xffffffffu, e, o);
        f += __shfl_xor_sync(0xffffffffu, f, o);
    }
    if (oi == 0 && base + ni < n) { elo[base + ni] = e; ero[base + ni] = f; }
}

// -------- fused softmax + aggregate, H=4, D=64 (2-pass, no max) -------------
template <int OUT_BF16>
__global__ void __launch_bounds__(256) gat_fused4(
    const int* __restrict__ rp, const int* __restrict__ cs,
    const float* __restrict__ el, const float* __restrict__ er,
    const float* __restrict__ feat, const float* __restrict__ bias,
    float* __restrict__ ebuf, float* __restrict__ outf,
    __nv_bfloat16* __restrict__ outhi, __nv_bfloat16* __restrict__ outlo)
{
    int warp = (blockIdx.x * blockDim.x + threadIdx.x) >> 5;
    int lane = threadIdx.x & 31;
    if (warp >= NN) return;
    int s0 = rp[warp], s1 = rp[warp + 1];

    float4 er4 = *(const float4*)&er[warp * 4];

    float t0 = 0.f, t1 = 0.f, t2 = 0.f, t3 = 0.f;
    for (int i = s0 + lane; i < s1; i += 32) {
        int sn = cs[i];
        float4 lv = *(const float4*)&el[sn * 4];
        lv.x += er4.x; lv.y += er4.y; lv.z += er4.z; lv.w += er4.w;
        lv.x = lv.x > 0.f ? lv.x : 0.2f * lv.x;
        lv.y = lv.y > 0.f ? lv.y : 0.2f * lv.y;
        lv.z = lv.z > 0.f ? lv.z : 0.2f * lv.z;
        lv.w = lv.w > 0.f ? lv.w : 0.2f * lv.w;
        lv.x = __expf(lv.x); lv.y = __expf(lv.y);
        lv.z = __expf(lv.z); lv.w = __expf(lv.w);
        *(float4*)&ebuf[i * 4] = lv;
        t0 += lv.x; t1 += lv.y; t2 += lv.z; t3 += lv.w;
    }
#pragma unroll
    for (int o = 16; o; o >>= 1) {
        t0 += __shfl_xor_sync(0xffffffffu, t0, o);
        t1 += __shfl_xor_sync(0xffffffffu, t1, o);
        t2 += __shfl_xor_sync(0xffffffffu, t2, o);
        t3 += __shfl_xor_sync(0xffffffffu, t3, o);
    }

    int hl = lane >> 3;
    float sv = hl == 0 ? t0 : hl == 1 ? t1 : hl == 2 ? t2 : t3;
    float inv = 1.f / sv;

    float a0 = 0.f, a1 = 0.f, a2 = 0.f, a3 = 0.f, a4 = 0.f, a5 = 0.f, a6 = 0.f, a7 = 0.f;
    int i = s0;
    for (; i + 2 <= s1; i += 2) {
        int sn0 = cs[i], sn1 = cs[i + 1];
        float aa0 = ebuf[i * 4 + hl] * inv;
        float aa1 = ebuf[(i + 1) * 4 + hl] * inv;
        const float4* fp0 = (const float4*)(feat + (size_t)sn0 * 256 + lane * 8);
        const float4* fp1 = (const float4*)(feat + (size_t)sn1 * 256 + lane * 8);
        float4 u0 = fp0[0], u1 = fp0[1];
        float4 w0 = fp1[0], w1 = fp1[1];
        a0 += aa0 * u0.x + aa1 * w0.x; a1 += aa0 * u0.y + aa1 * w0.y;
        a2 += aa0 * u0.z + aa1 * w0.z; a3 += aa0 * u0.w + aa1 * w0.w;
        a4 += aa0 * u1.x + aa1 * w1.x; a5 += aa0 * u1.y + aa1 * w1.y;
        a6 += aa0 * u1.z + aa1 * w1.z; a7 += aa0 * u1.w + aa1 * w1.w;
    }
    if (i < s1) {
        int sn = cs[i];
        float a = ebuf[i * 4 + hl] * inv;
        const float4* fp = (const float4*)(feat + (size_t)sn * 256 + lane * 8);
        float4 v0 = fp[0], v1 = fp[1];
        a0 += a * v0.x; a1 += a * v0.y; a2 += a * v0.z; a3 += a * v0.w;
        a4 += a * v1.x; a5 += a * v1.y; a6 += a * v1.z; a7 += a * v1.w;
    }
    const float4* bp = (const float4*)(bias + lane * 8);
    float4 b0 = bp[0], b1 = bp[1];
    float r[8] = { a0 + b0.x, a1 + b0.y, a2 + b0.z, a3 + b0.w,
                   a4 + b1.x, a5 + b1.y, a6 + b1.z, a7 + b1.w };
    if (OUT_BF16) {
        __nv_bfloat16 hi[8], lo[8];
#pragma unroll
        for (int q = 0; q < 8; q++) {
            hi[q] = __float2bfloat16(r[q]);
            lo[q] = __float2bfloat16(r[q] - __bfloat162float(hi[q]));
        }
        *(uint4*)(outhi + (size_t)warp * 256 + lane * 8) = *(const uint4*)hi;
        *(uint4*)(outlo + (size_t)warp * 256 + lane * 8) = *(const uint4*)lo;
    } else {
        float4* op = (float4*)(outf + (size_t)warp * 256 + lane * 8);
        op[0] = make_float4(r[0], r[1], r[2], r[3]);
        op[1] = make_float4(r[4], r[5], r[6], r[7]);
    }
}

// -------- fused softmax + aggregate, H=1, D=16 (2-pass, no max) -------------
__global__ void __launch_bounds__(256) gat_fused1(
    const int* __restrict__ rp, const int* __restrict__ cs,
    const float* __restrict__ el, const float* __restrict__ er,
    const float* __restrict__ feat, const float* __restrict__ bias,
    float* __restrict__ ebuf, float* __restrict__ out)
{
    int warp = (blockIdx.x * blockDim.x + threadIdx.x) >> 5;
    int lane = threadIdx.x & 31;
    if (warp >= NN) return;
    int s0 = rp[warp], s1 = rp[warp + 1];
    float erv = er[warp];

    float t = 0.f;
    for (int i = s0 + lane; i < s1; i += 32) {
        float x = el[cs[i]] + erv;
        x = x > 0.f ? x : 0.2f * x;
        float v = __expf(x);
        ebuf[i] = v;
        t += v;
    }
#pragma unroll
    for (int o = 16; o; o >>= 1) t += __shfl_xor_sync(0xffffffffu, t, o);
    float inv = 1.f / t;

    int half = lane >> 4, dk = lane & 15;
    float acc = 0.f;
    for (int i = s0 + half; i < s1; i += 2) {
        int sn = cs[i];
        float a = ebuf[i] * inv;
        acc += a * feat[(size_t)sn * 16 + dk];
    }
    acc += __shfl_xor_sync(0xffffffffu, acc, 16);
    if (lane < 16) out[(size_t)warp * 16 + lane] = acc + bias[lane];
}

// ---------------------------------------------------------------------------
extern "C" void kernel_launch(void* const* d_in, const int* in_sizes, int n_in,
                              void* d_out, int out_size) {
    const float* inputs = (const float*)d_in[0];
    const float* W0 = (const float*)d_in[1];
    const float* al0 = (const float*)d_in[2];
    const float* ar0 = (const float*)d_in[3];
    const float* b0 = (const float*)d_in[4];
    const float* W1 = (const float*)d_in[5];
    const float* al1 = (const float*)d_in[6];
    const float* ar1 = (const float*)d_in[7];
    const float* b1 = (const float*)d_in[8];
    const float* W2 = (const float*)d_in[9];
    const float* al2 = (const float*)d_in[10];
    const float* ar2 = (const float*)d_in[11];
    const float* b2 = (const float*)d_in[12];
    const int* src = (const int*)d_in[13];
    const int* dst = (const int*)d_in[14];

    float *feat, *h, *elA, *erA, *elB, *erB, *ebuf;
    int *cnt, *rpp, *cur, *csrc, *bsum;
    __nv_bfloat16 *Ahi, *Alo, *Whi, *Wlo, *Whi2, *Wlo2;
    cudaGetSymbolAddress((void**)&feat, g_feat);
    cudaGetSymbolAddress((void**)&h, g_h);
    cudaGetSymbolAddress((void**)&elA, g_el);
    cudaGetSymbolAddress((void**)&erA, g_er);
    cudaGetSymbolAddress((void**)&elB, g_el2);
    cudaGetSymbolAddress((void**)&erB, g_er2);
    cudaGetSymbolAddress((void**)&ebuf, g_e);
    cudaGetSymbolAddress((void**)&cnt, g_cnt);
    cudaGetSymbolAddress((void**)&rpp, g_rp);
    cudaGetSymbolAddress((void**)&cur, g_cur);
    cudaGetSymbolAddress((void**)&csrc, g_csrc);
    cudaGetSymbolAddress((void**)&bsum, g_bsum);
    cudaGetSymbolAddress((void**)&Ahi, g_Ahi);
    cudaGetSymbolAddress((void**)&Alo, g_Alo);
    cudaGetSymbolAddress((void**)&Whi, g_Whi);
    cudaGetSymbolAddress((void**)&Wlo, g_Wlo);
    cudaGetSymbolAddress((void**)&Whi2, g_Whi2);
    cudaGetSymbolAddress((void**)&Wlo2, g_Wlo2);

    cudaFuncSetAttribute(hmma_gemm, cudaFuncAttributeMaxDynamicSharedMemorySize, HMMA_SMEM);

    int warpBlocks = (NN * 32 + 255) / 256;
    dim3 mmaGrid(2, (NN + 127) / 128);

    // fork/join: side stream runs the CSR build + layer-1 W convert
    // concurrently with the layer-0 dense path.
    cudaStream_t sB;
    cudaEvent_t evFork, evCSR, evW1;
    cudaStreamCreateWithFlags(&sB, cudaStreamNonBlocking);
    cudaEventCreateWithFlags(&evFork, cudaEventDisableTiming);
    cudaEventCreateWithFlags(&evCSR, cudaEventDisableTiming);
    cudaEventCreateWithFlags(&evW1, cudaEventDisableTiming);

    cudaEventRecord(evFork, 0);
    cudaStreamWaitEvent(sB, evFork, 0);

    // ---- side stream: CSR build, then convW for layer 1 (into W2 buffers) --
    init_cnt<<<(NN + 255) / 256, 256, 0, sB>>>(cnt);
    hist_kernel<<<(NE + 255) / 256, 256, 0, sB>>>(dst, cnt);
    scan_p1<<<SCAN_BLOCKS, 256, 0, sB>>>(cnt, bsum);
    scan_p2<<<1, 256, 0, sB>>>(bsum);
    scan_p3<<<SCAN_BLOCKS, 32, 0, sB>>>(cnt, bsum, rpp, cur);
    scatter_kernel<<<(NE + 255) / 256, 256, 0, sB>>>(src, dst, cur, csrc);
    cudaEventRecord(evCSR, sB);
    convW_kernel<<<(256 * 256 + 255) / 256, 256, 0, sB>>>(W1, Whi2, Wlo2, 256, elB, erB);
    cudaEventRecord(evW1, sB);

    // ---- main stream: layer-0 dense path -----------------------------------
    convA_kernel<<<(NN * 128 / 4 + 255) / 256, 256>>>(inputs, Ahi, Alo, NN * 128 / 4);
    convW_kernel<<<(128 * 256 + 255) / 256, 256>>>(W0, Whi, Wlo, 128, elA, erA);
    hmma_gemm<<<mmaGrid, 256, HMMA_SMEM>>>(Ahi, Alo, Whi, Wlo, feat, NN, 128,
                                           al0, ar0, elA, erA);
    cudaStreamWaitEvent(0, evCSR, 0);
    gat_fused4<1><<<warpBlocks, 256>>>(rpp, csrc, elA, erA, feat, b0, ebuf,
                                       nullptr, Ahi, Alo);

    // ---- layer 1 -----------------------------------------------------------
    cudaStreamWaitEvent(0, evW1, 0);
    hmma_gemm<<<mmaGrid, 256, HMMA_SMEM>>>(Ahi, Alo, Whi2, Wlo2, feat, NN, 256,
                                           al1, ar1, elB, erB);
    gat_fused4<0><<<warpBlocks, 256>>>(rpp, csrc, elB, erB, feat, b1, ebuf,
                                       h, nullptr, nullptr);

    // ---- layer 2 -----------------------------------------------------------
    float* out = (float*)d_out;
    gemm16<<<(NN + 15) / 16, 256>>>(h, W2, feat, NN, al2, ar2, elA, erA);
    gat_fused1<<<warpBlocks, 256>>>(rpp, csrc, elA, erA, feat, b2, ebuf, out);

    cudaEventDestroy(evFork);
    cudaEventDestroy(evCSR);
    cudaEventDestroy(evW1);
    cudaStreamDestroy(sB);
}